// round 13
// baseline (speedup 1.0000x reference)
#include <cuda_runtime.h>
#include <cuda_fp16.h>
#include <math.h>
#include <stdint.h>

#define M_ROWS 32768          // B*N
#define NB 32
#define NNODE 1024
#define NN2 (1024u * 1024u)

// weight offsets in g_W16 (half2 units); layout [k2][128] interleaved
#define OFF_RAW 0
#define OFF_D0  4096
#define OFF_D1  8192
#define OFF_Q0  16384
#define OFF_K0  32768
#define OFF_V0  49152
#define OFF_O0  65536
#define OFF_Q1  73728
#define OFF_K1  90112
#define OFF_V1  106496
#define OFF_O1  122880

// ---------------- scratch (device globals, allocation-free) ----------------
__device__ float   g_Q[2u * NN2];
__device__ __half2 g_W16[131072];
__device__ __half  g_X16[(size_t)M_ROWS * 64];
__device__ __half  g_hp [(size_t)M_ROWS * 128];
__device__ __half  g_h  [(size_t)M_ROWS * 128];
__device__ __half  g_h2 [(size_t)M_ROWS * 128];
__device__ __half  g_qb [(size_t)M_ROWS * 128];
__device__ __half  g_kb [(size_t)M_ROWS * 128];
__device__ __half  g_vb [(size_t)M_ROWS * 128];
__device__ __half  g_ctx[(size_t)M_ROWS * 128];

// ---------------- helpers ----------------
__device__ __forceinline__ uint32_t f2h2(float a, float b) {
    __half2 h = __floats2half2_rn(a, b);
    return *reinterpret_cast<uint32_t*>(&h);
}
__device__ __forceinline__ uint32_t h2bits(__half2 h) {
    return *reinterpret_cast<uint32_t*>(&h);
}
__device__ __forceinline__ float ex2f(float x) {
    float r;
    asm("ex2.approx.ftz.f32 %0, %1;" : "=f"(r) : "f"(x));
    return r;
}
__device__ __forceinline__ void cp16(uint32_t dst_smem, const void* src) {
    asm volatile("cp.async.ca.shared.global [%0], [%1], 16;\n"
                 :: "r"(dst_smem), "l"(src));
}
__device__ __forceinline__ void cp_commit() {
    asm volatile("cp.async.commit_group;\n");
}
__device__ __forceinline__ void cp_wait0() {
    asm volatile("cp.async.wait_group 0;\n");
}
__device__ __forceinline__ uint32_t smem_u32(const void* p) {
    return (uint32_t)__cvta_generic_to_shared(p);
}

__device__ __forceinline__ void mma_f16(float* d, const uint32_t* a,
                                        const uint32_t* b, const float* c) {
    asm volatile(
        "mma.sync.aligned.m16n8k16.row.col.f32.f16.f16.f32 "
        "{%0,%1,%2,%3}, {%4,%5,%6,%7}, {%8,%9}, {%10,%11,%12,%13};\n"
        : "=f"(d[0]), "=f"(d[1]), "=f"(d[2]), "=f"(d[3])
        : "r"(a[0]), "r"(a[1]), "r"(a[2]), "r"(a[3]),
          "r"(b[0]), "r"(b[1]),
          "f"(c[0]), "f"(c[1]), "f"(c[2]), "f"(c[3]));
}

// ---------------- Q[l] = sum_k softmax(theta)[l,k] * T[l,k] ----------------
__global__ void qmix_kernel(const float* __restrict__ T,
                            const float* __restrict__ th) {
    size_t i = (size_t)blockIdx.x * 256 + threadIdx.x;
    size_t l  = i >> 20;
    size_t ij = i & (NN2 - 1);
    float a = th[l*3+0], b = th[l*3+1], c = th[l*3+2];
    float m = fmaxf(a, fmaxf(b, c));
    float ea = __expf(a - m), eb = __expf(b - m), ec = __expf(c - m);
    float inv = 1.f / (ea + eb + ec);
    const float* Tl = T + l * 3u * NN2;
    g_Q[i] = inv * (ea * Tl[ij] + eb * Tl[NN2 + ij] + ec * Tl[2u*NN2 + ij]);
}

// ---------------- fp32 -> fp16 cast (for X) ----------------
__global__ void tohalf_kernel(const float* __restrict__ x, __half* __restrict__ o) {
    size_t i = ((size_t)blockIdx.x * 256 + threadIdx.x) * 4;
    float4 v = *reinterpret_cast<const float4*>(x + i);
    uint2 u;
    u.x = f2h2(v.x, v.y);
    u.y = f2h2(v.z, v.w);
    *reinterpret_cast<uint2*>(o + i) = u;
}

// ------- weight convert + interleave -------
__global__ void wconv_kernel(
    const float* r,  const float* d0, const float* d1,
    const float* q0, const float* k0, const float* v0, const float* o0,
    const float* q1, const float* k1, const float* v1, const float* o1)
{
    const float* srcs[11] = {r, d0, d1, q0, k0, v0, o0, q1, k1, v1, o1};
    const int    Ks[11]   = {64, 64, 128, 256, 256, 256, 128, 256, 256, 256, 128};
    const int    offs[11] = {OFF_RAW, OFF_D0, OFF_D1, OFF_Q0, OFF_K0, OFF_V0,
                             OFF_O0, OFF_Q1, OFF_K1, OFF_V1, OFF_O1};
    int m   = blockIdx.y;
    int idx = blockIdx.x * 256 + threadIdx.x;
    int K   = Ks[m];
    if (idx >= K * 64) return;
    const float* s = srcs[m];
    int k2 = idx >> 7, n = idx & 127;
    g_W16[offs[m] + idx] =
        __floats2half2_rn(s[(2*k2)*128 + n], s[(2*k2 + 1)*128 + n]);
}

// ---------- shared GEMM body (device function) ----------
struct GemmSmem {
    uint32_t As[2][128][20];
    uint32_t Bs[2][16][136];
};

__device__ __forceinline__ void hgemm_body(
    GemmSmem* sm,
    const __half* A1, const __half* A2, int K1, int K,
    const __half2* W2, const float* bias,
    const __half* base, __half* C, int relu, int row0)
{
    const int tid  = threadIdx.x;
    const int lane = tid & 31;
    const int w    = tid >> 5;
    const int wm   = w & 3;
    const int wn   = w >> 2;
    const int lr   = lane >> 2;
    const int lc   = lane & 3;
    const int sa_r   = tid >> 1;
    const int sa_k16 = (tid & 1) << 4;

#define CP_A(k0, bufi)                                                         \
    {                                                                          \
        int kg = (k0) + sa_k16;                                                \
        const __half* src = (kg < K1) ? A1 : A2;                               \
        int kk     = (kg < K1) ? kg : (kg - K1);                               \
        int stride = (kg < K1) ? K1 : (K - K1);                                \
        const __half* p = src + (size_t)(row0 + sa_r) * stride + kk;           \
        uint32_t d = smem_u32(&sm->As[bufi][sa_r][sa_k16 >> 1]);               \
        cp16(d, p);                                                            \
        cp16(d + 16, p + 8);                                                   \
    }

#define CP_B(k0, bufi)                                                         \
    {                                                                          \
        _Pragma("unroll")                                                      \
        for (int i = 0; i < 2; ++i) {                                          \
            int idx = tid + i * 256;                                           \
            int k2r = idx >> 5, nq = (idx & 31) << 2;                          \
            cp16(smem_u32(&sm->Bs[bufi][k2r][nq]),                             \
                 W2 + (size_t)(((k0) >> 1) + k2r) * 128 + nq);                 \
        }                                                                      \
    }

    float acc[2][8][4];
#pragma unroll
    for (int mt = 0; mt < 2; ++mt)
#pragma unroll
        for (int nt = 0; nt < 8; ++nt)
#pragma unroll
            for (int i = 0; i < 4; ++i) acc[mt][nt][i] = 0.f;

    CP_A(0, 0);
    CP_B(0, 0);
    cp_commit();

    int buf = 0;
    for (int k0 = 0; k0 < K; k0 += 32) {
        cp_wait0();
        __syncthreads();
        const bool has_next = (k0 + 32 < K);
        if (has_next) {
            CP_A(k0 + 32, buf ^ 1);
            CP_B(k0 + 32, buf ^ 1);
            cp_commit();
        }
#pragma unroll
        for (int s = 0; s < 2; ++s) {
            uint32_t a[2][4], b[8][2];
#pragma unroll
            for (int mt = 0; mt < 2; ++mt) {
                int rm = wm*32 + mt*16 + lr;
                a[mt][0] = sm->As[buf][rm    ][s*8 + lc    ];
                a[mt][1] = sm->As[buf][rm + 8][s*8 + lc    ];
                a[mt][2] = sm->As[buf][rm    ][s*8 + lc + 4];
                a[mt][3] = sm->As[buf][rm + 8][s*8 + lc + 4];
            }
#pragma unroll
            for (int nt = 0; nt < 8; ++nt) {
                int nb = wn*64 + nt*8 + lr;
                b[nt][0] = sm->Bs[buf][s*8 + lc    ][nb];
                b[nt][1] = sm->Bs[buf][s*8 + lc + 4][nb];
            }
#pragma unroll
            for (int mt = 0; mt < 2; ++mt)
#pragma unroll
                for (int nt = 0; nt < 8; ++nt)
                    mma_f16(acc[mt][nt], a[mt], b[nt], acc[mt][nt]);
        }
        buf ^= 1;
    }

#pragma unroll
    for (int mt = 0; mt < 2; ++mt) {
#pragma unroll
        for (int nt = 0; nt < 8; ++nt) {
            int col = wn*64 + nt*8 + 2*lc;
            float b0 = bias[col], b1 = bias[col+1];
#pragma unroll
            for (int half = 0; half < 2; ++half) {
                int row = row0 + wm*32 + mt*16 + lr + half*8;
                float v0 = acc[mt][nt][half*2+0] + b0;
                float v1 = acc[mt][nt][half*2+1] + b1;
                if (relu) { v0 = fmaxf(v0, 0.f); v1 = fmaxf(v1, 0.f); }
                if (base) {
                    __half2 bh = *reinterpret_cast<const __half2*>(
                        base + (size_t)row * 128 + col);
                    float2 bf = __half22float2(bh);
                    v0 += bf.x; v1 += bf.y;
                }
                *reinterpret_cast<uint32_t*>(C + (size_t)row * 128 + col) =
                    f2h2(v0, v1);
            }
        }
    }
#undef CP_A
#undef CP_B
}

__global__ __launch_bounds__(256) void hgemm_kernel(
    const __half* __restrict__ A1, const __half* __restrict__ A2, int K1, int K,
    const __half2* __restrict__ W2, const float* __restrict__ bias,
    const __half* __restrict__ base, __half* __restrict__ C, int relu)
{
    __shared__ GemmSmem sm;
    hgemm_body(&sm, A1, A2, K1, K, W2, bias, base, C, relu, blockIdx.x << 7);
}

// batched q/k/v: blockIdx.y selects the matrix
__global__ __launch_bounds__(256) void qkv3_kernel(
    const __half* __restrict__ A1, const __half* __restrict__ A2,
    const __half2* __restrict__ Wq, const __half2* __restrict__ Wk,
    const __half2* __restrict__ Wv,
    const float* __restrict__ bq, const float* __restrict__ bk,
    const float* __restrict__ bv,
    __half* __restrict__ Oq, __half* __restrict__ Ok, __half* __restrict__ Ov)
{
    __shared__ GemmSmem sm;
    const int m = blockIdx.y;
    const __half2* W2 = (m == 0) ? Wq : (m == 1) ? Wk : Wv;
    const float* bias = (m == 0) ? bq : (m == 1) ? bk : bv;
    __half* C         = (m == 0) ? Oq : (m == 1) ? Ok : Ov;
    hgemm_body(&sm, A1, A2, 128, 256, W2, bias, nullptr, C, 0, blockIdx.x << 7);
}

// ====== fused mask+diffusion+linear: Hout = relu((half(Q⊙A) @ Hin) @ Wd + b) ======
// Phase 1 stages half(Q[i,j]*A[b,i,j]) on the fly (Q is L2-resident, A from DRAM).
template<int BN>
__global__ __launch_bounds__(256, 2) void diff_fused_kernel(
    const float* __restrict__ Qm, const float* __restrict__ Adj,
    const __half* __restrict__ Hin,
    const __half2* __restrict__ Wd2, const float* __restrict__ bias,
    __half* __restrict__ Hout)
{
    constexpr int WN = BN / 2;
    constexpr int NT = WN / 8;
    constexpr int ZW = BN / 2 + 4;

    extern __shared__ uint32_t dsm[];
    uint32_t* AS = dsm;                    // [2][128][20]
    uint32_t* BS = dsm + 5120;             // [2][16][136]
    uint32_t* ZS = dsm + 5120 + 4352;      // [128][ZW]
#define ASX(bufi, r, c) AS[(bufi)*2560 + (r)*20 + (c)]
#define BSX(bufi, r, c) BS[(bufi)*2176 + (r)*136 + (c)]
#define ZSX(r, c)       ZS[(r)*ZW + (c)]

    const int tid  = threadIdx.x;
    const int lane = tid & 31;
    const int w    = tid >> 5;
    const int wm   = w & 3;
    const int wn   = w >> 2;
    const int lr   = lane >> 2;
    const int lc   = lane & 3;
    const int b    = blockIdx.z;
    const int i0   = blockIdx.x << 7;
    const size_t ab = (size_t)b * NN2;
    const size_t hb = (size_t)b * NNODE * BN;

    const int sa_r   = tid >> 1;
    const int sa_k16 = (tid & 1) << 4;

    float4 pa4[4], pq4[4];
    uint4 bu0, bu1;

#define LDG_AQ(j0)                                                             \
    {                                                                          \
        size_t off = (size_t)(i0 + sa_r) * NNODE + (j0) + sa_k16;              \
        const float* ap = Adj + ab + off;                                      \
        const float* qp = Qm + off;                                            \
        _Pragma("unroll")                                                      \
        for (int jj = 0; jj < 4; ++jj) {                                       \
            pa4[jj] = *reinterpret_cast<const float4*>(ap + 4*jj);             \
            pq4[jj] = *reinterpret_cast<const float4*>(qp + 4*jj);             \
        }                                                                      \
    }

#define STS_AQ(bufi)                                                           \
    {                                                                          \
        _Pragma("unroll")                                                      \
        for (int jj = 0; jj < 2; ++jj) {                                       \
            uint4 u;                                                           \
            u.x = f2h2(pq4[2*jj].x*pa4[2*jj].x,     pq4[2*jj].y*pa4[2*jj].y);  \
            u.y = f2h2(pq4[2*jj].z*pa4[2*jj].z,     pq4[2*jj].w*pa4[2*jj].w);  \
            u.z = f2h2(pq4[2*jj+1].x*pa4[2*jj+1].x, pq4[2*jj+1].y*pa4[2*jj+1].y);\
            u.w = f2h2(pq4[2*jj+1].z*pa4[2*jj+1].z, pq4[2*jj+1].w*pa4[2*jj+1].w);\
            *reinterpret_cast<uint4*>(&ASX(bufi, sa_r, (sa_k16>>1) + 4*jj)) = u;\
        }                                                                      \
    }

#define DIFF_LDG_B(j0)                                                         \
    {                                                                          \
        if (BN == 128) {                                                       \
            int k2r = tid >> 4, nh = (tid & 15) * 8;                           \
            const __half* q = Hin + hb + (size_t)((j0) + 2*k2r) * BN + nh;     \
            bu0 = *reinterpret_cast<const uint4*>(q);                          \
            bu1 = *reinterpret_cast<const uint4*>(q + BN);                     \
        } else {                                                               \
            int k2r = tid >> 4, nh = (tid & 15) * 4;                           \
            const __half* q = Hin + hb + (size_t)((j0) + 2*k2r) * BN + nh;     \
            uint2 t0 = *reinterpret_cast<const uint2*>(q);                     \
            uint2 t1 = *reinterpret_cast<const uint2*>(q + BN);                \
            bu0.x = t0.x; bu0.y = t0.y; bu1.x = t1.x; bu1.y = t1.y;            \
        }                                                                      \
    }

#define DIFF_STS_B(bufi)                                                       \
    {                                                                          \
        if (BN == 128) {                                                       \
            int k2r = tid >> 4, nh = (tid & 15) * 8;                           \
            uint4 v0, v1;                                                      \
            v0.x = __byte_perm(bu0.x, bu1.x, 0x5410);                          \
            v0.y = __byte_perm(bu0.x, bu1.x, 0x7632);                          \
            v0.z = __byte_perm(bu0.y, bu1.y, 0x5410);                          \
            v0.w = __byte_perm(bu0.y, bu1.y, 0x7632);                          \
            v1.x = __byte_perm(bu0.z, bu1.z, 0x5410);                          \
            v1.y = __byte_perm(bu0.z, bu1.z, 0x7632);                          \
            v1.z = __byte_perm(bu0.w, bu1.w, 0x5410);                          \
            v1.w = __byte_perm(bu0.w, bu1.w, 0x7632);                          \
            *reinterpret_cast<uint4*>(&BSX(bufi, k2r, nh    )) = v0;           \
            *reinterpret_cast<uint4*>(&BSX(bufi, k2r, nh + 4)) = v1;           \
        } else {                                                               \
            int k2r = tid >> 4, nh = (tid & 15) * 4;                           \
            uint4 v0;                                                          \
            v0.x = __byte_perm(bu0.x, bu1.x, 0x5410);                          \
            v0.y = __byte_perm(bu0.x, bu1.x, 0x7632);                          \
            v0.z = __byte_perm(bu0.y, bu1.y, 0x5410);                          \
            v0.w = __byte_perm(bu0.y, bu1.y, 0x7632);                          \
            *reinterpret_cast<uint4*>(&BSX(bufi, k2r, nh)) = v0;               \
        }                                                                      \
    }

    // ---------------- phase 1: z = half(Q⊙A) @ Hin ----------------
    float acc[2][NT][4];
#pragma unroll
    for (int mt = 0; mt < 2; ++mt)
#pragma unroll
        for (int nt = 0; nt < NT; ++nt)
#pragma unroll
            for (int i = 0; i < 4; ++i) acc[mt][nt][i] = 0.f;

    LDG_AQ(0);
    DIFF_LDG_B(0);
    STS_AQ(0);
    DIFF_STS_B(0);
    __syncthreads();

    int buf = 0;
    for (int j0 = 0; j0 < NNODE; j0 += 32) {
        const bool has_next = (j0 + 32 < NNODE);
        if (has_next) {
            LDG_AQ(j0 + 32);
            DIFF_LDG_B(j0 + 32);
        }
#pragma unroll
        for (int s = 0; s < 2; ++s) {
            uint32_t a[2][4], bf[NT][2];
#pragma unroll
            for (int mt = 0; mt < 2; ++mt) {
                int rm = wm*32 + mt*16 + lr;
                a[mt][0] = ASX(buf, rm    , s*8 + lc    );
                a[mt][1] = ASX(buf, rm + 8, s*8 + lc    );
                a[mt][2] = ASX(buf, rm    , s*8 + lc + 4);
                a[mt][3] = ASX(buf, rm + 8, s*8 + lc + 4);
            }
#pragma unroll
            for (int nt = 0; nt < NT; ++nt) {
                int nb = wn*WN + nt*8 + lr;
                bf[nt][0] = BSX(buf, s*8 + lc    , nb);
                bf[nt][1] = BSX(buf, s*8 + lc + 4, nb);
            }
#pragma unroll
            for (int mt = 0; mt < 2; ++mt)
#pragma unroll
                for (int nt = 0; nt < NT; ++nt)
                    mma_f16(acc[mt][nt], a[mt], bf[nt], acc[mt][nt]);
        }
        if (has_next) {
            STS_AQ(buf ^ 1);
            DIFF_STS_B(buf ^ 1);
        }
        __syncthreads();
        buf ^= 1;
    }

#pragma unroll
    for (int mt = 0; mt < 2; ++mt) {
#pragma unroll
        for (int nt = 0; nt < NT; ++nt) {
            int col = wn*WN + nt*8 + 2*lc;
#pragma unroll
            for (int half = 0; half < 2; ++half) {
                int row = wm*32 + mt*16 + lr + half*8;
                ZSX(row, col >> 1) =
                    f2h2(acc[mt][nt][half*2+0], acc[mt][nt][half*2+1]);
            }
        }
    }
    __syncthreads();

    // ---------------- phase 2: Hout = relu(z @ Wd + bias) ----------------
#define CP_W(k0, bufi)                                                         \
    {                                                                          \
        _Pragma("unroll")                                                      \
        for (int i = 0; i < 2; ++i) {                                          \
            int idx = tid + i * 256;                                           \
            int k2r = idx >> 5, nq = (idx & 31) << 2;                          \
            cp16(smem_u32(&BSX(bufi, k2r, nq)),                                \
                 Wd2 + (size_t)(((k0) >> 1) + k2r) * 128 + nq);                \
        }                                                                      \
    }

    float acc2[2][8][4];
#pragma unroll
    for (int mt = 0; mt < 2; ++mt)
#pragma unroll
        for (int nt = 0; nt < 8; ++nt)
#pragma unroll
            for (int i = 0; i < 4; ++i) acc2[mt][nt][i] = 0.f;

    CP_W(0, 0);
    cp_commit();

    buf = 0;
    for (int k0 = 0; k0 < BN; k0 += 32) {
        cp_wait0();
        __syncthreads();
        const bool has_next = (k0 + 32 < BN);
        if (has_next) {
            CP_W(k0 + 32, buf ^ 1);
            cp_commit();
        }
        const int k2b = k0 >> 1;
#pragma unroll
        for (int s = 0; s < 2; ++s) {
            uint32_t a[2][4], bfr[8][2];
#pragma unroll
            for (int mt = 0; mt < 2; ++mt) {
                int rm = wm*32 + mt*16 + lr;
                a[mt][0] = ZSX(rm    , k2b + s*8 + lc    );
                a[mt][1] = ZSX(rm + 8, k2b + s*8 + lc    );
                a[mt][2] = ZSX(rm    , k2b + s*8 + lc + 4);
                a[mt][3] = ZSX(rm + 8, k2b + s*8 + lc + 4);
            }
#pragma unroll
            for (int nt = 0; nt < 8; ++nt) {
                int nb = wn*64 + nt*8 + lr;
                bfr[nt][0] = BSX(buf, s*8 + lc    , nb);
                bfr[nt][1] = BSX(buf, s*8 + lc + 4, nb);
            }
#pragma unroll
            for (int mt = 0; mt < 2; ++mt)
#pragma unroll
                for (int nt = 0; nt < 8; ++nt)
                    mma_f16(acc2[mt][nt], a[mt], bfr[nt], acc2[mt][nt]);
        }
        buf ^= 1;
    }

#pragma unroll
    for (int mt = 0; mt < 2; ++mt) {
#pragma unroll
        for (int nt = 0; nt < 8; ++nt) {
            int col = wn*64 + nt*8 + 2*lc;
            float b0 = bias[col], b1 = bias[col+1];
#pragma unroll
            for (int half = 0; half < 2; ++half) {
                int row = i0 + wm*32 + mt*16 + lr + half*8;
                float v0 = fmaxf(acc2[mt][nt][half*2+0] + b0, 0.f);
                float v1 = fmaxf(acc2[mt][nt][half*2+1] + b1, 0.f);
                *reinterpret_cast<uint32_t*>(
                    Hout + ((size_t)b * NNODE + row) * 128 + col) = f2h2(v0, v1);
            }
        }
    }
#undef LDG_AQ
#undef STS_AQ
#undef DIFF_LDG_B
#undef DIFF_STS_B
#undef CP_W
#undef ASX
#undef BSX
#undef ZSX
}

// ========== fp16 flash attention: 256 q / 512 thr; P register-resident ==========
__global__ __launch_bounds__(512) void attn_mma_kernel(
    const __half* __restrict__ Qg, const __half* __restrict__ Kg,
    const __half* __restrict__ Vg, __half* __restrict__ Og)
{
    extern __shared__ uint32_t asmem[];
    uint32_t (*Ps2)[36] = reinterpret_cast<uint32_t(*)[36]>(asmem);            // 256 rows (Q staging only)
    uint32_t (*Ks2)[36] = reinterpret_cast<uint32_t(*)[36]>(asmem + 256*36);   // 2*64 rows
    uint32_t (*Vs2)[72] = reinterpret_cast<uint32_t(*)[72]>(asmem + 384*36);   // 2*32 rows

    const int tid  = threadIdx.x;
    const int lane = tid & 31;
    const int w    = tid >> 5;
    const int lr   = lane >> 2;
    const int lc   = lane & 3;
    const int b    = blockIdx.z, h = blockIdx.y;
    const int q0   = blockIdx.x << 8;
    const size_t rb = (size_t)b * NNODE;
    const int hoff = h * 64;
    const float SC = 0.125f * 1.4426950408889634f;
    const __half2 h2sc = __float2half2_rn(SC);

    {
        int r   = w*16 + (lane >> 1);
        int seg = (lane & 1) * 32;
        const __half* p = Qg + (rb + q0 + r) * 128 + hoff + seg;
#pragma unroll
        for (int jj = 0; jj < 4; ++jj) {
            uint4 u = *reinterpret_cast<const uint4*>(p + 8*jj);
            *reinterpret_cast<uint4*>(&Ps2[r][(seg>>1) + 4*jj]) = u;
        }
    }
    __syncwarp();

    uint32_t qa[4][4];
#pragma unroll
    for (int ks = 0; ks < 4; ++ks) {
        qa[ks][0] = Ps2[w*16 + lr    ][ks*8 + lc    ];
        qa[ks][1] = Ps2[w*16 + lr + 8][ks*8 + lc    ];
        qa[ks][2] = Ps2[w*16 + lr    ][ks*8 + lc + 4];
        qa[ks][3] = Ps2[w*16 + lr + 8][ks*8 + lc + 4];
#pragma unroll
        for (int i = 0; i < 4; ++i) {
            __half2 hv = *reinterpret_cast<__half2*>(&qa[ks][i]);
            hv = __hmul2(hv, h2sc);
            qa[ks][i] = h2bits(hv);
        }
    }

    float m0 = -1e30f, m1 = -1e30f, l0 = 0.f, l1 = 0.f;
    float oacc[8][4];
#pragma unroll
    for (int nt = 0; nt < 8; ++nt)
#pragma unroll
        for (int i = 0; i < 4; ++i) oacc[nt][i] = 0.f;

    uint2 uv0, uv1;
    const int kr   = tid >> 3;
    const int kseg = (tid & 7) << 3;
    const int vk2r = tid >> 4;
    const int vdq  = (tid & 15) * 4;

#define CP_K(j0, bufi)                                                         \
    {                                                                          \
        const __half* p = Kg + (rb + (j0) + kr) * 128 + hoff + kseg;           \
        cp16(smem_u32(&Ks2[(bufi)*64 + kr][kseg >> 1]), p);                    \
    }

#define LDG_V(j0)                                                              \
    {                                                                          \
        const __half* q = Vg + (rb + (j0) + 2*vk2r) * 128 + hoff + vdq;        \
        uv0 = *reinterpret_cast<const uint2*>(q);                              \
        uv1 = *reinterpret_cast<const uint2*>(q + 128);                        \
    }

#define STS_V(bufi)                                                            \
    {                                                                          \
        uint4 v0;                                                              \
        v0.x = __byte_perm(uv0.x, uv1.x, 0x5410);                              \
        v0.y = __byte_perm(uv0.x, uv1.x, 0x7632);                              \
        v0.z = __byte_perm(uv0.y, uv1.y, 0x5410);                              \
        v0.w = __byte_perm(uv0.y, uv1.y, 0x7632);                              \
        *reinterpret_cast<uint4*>(&Vs2[(bufi)*32 + vk2r][vdq]) = v0;           \
    }

    CP_K(0, 0);
    cp_commit();
    LDG_V(0);
    STS_V(0);

    for (int c = 0; c < NNODE/64; ++c) {
        const int buf = c & 1;
        cp_wait0();
        __syncthreads();

        const bool has_next = (c + 1 < NNODE/64);
        if (has_next) {
            CP_K((c + 1) * 64, buf ^ 1);
            cp_commit();
            LDG_V((c + 1) * 64);
        }

        float sacc[8][4];
#pragma unroll
        for (int nt = 0; nt < 8; ++nt)
#pragma unroll
            for (int i = 0; i < 4; ++i) sacc[nt][i] = 0.f;
#pragma unroll
        for (int ks = 0; ks < 4; ++ks) {
#pragma unroll
            for (int nt = 0; nt < 8; ++nt) {
                uint32_t bf[2];
                bf[0] = Ks2[buf*64 + nt*8 + lr][ks*8 + lc    ];
                bf[1] = Ks2[buf*64 + nt*8 + lr][ks*8 + lc + 4];
                mma_f16(sacc[nt], qa[ks], bf, sacc[nt]);
            }
        }

        float rmax0 = -1e30f, rmax1 = -1e30f;
#pragma unroll
        for (int nt = 0; nt < 8; ++nt) {
            rmax0 = fmaxf(rmax0, fmaxf(sacc[nt][0], sacc[nt][1]));
            rmax1 = fmaxf(rmax1, fmaxf(sacc[nt][2], sacc[nt][3]));
        }
        rmax0 = fmaxf(rmax0, __shfl_xor_sync(0xffffffffu, rmax0, 1));
        rmax0 = fmaxf(rmax0, __shfl_xor_sync(0xffffffffu, rmax0, 2));
        rmax1 = fmaxf(rmax1, __shfl_xor_sync(0xffffffffu, rmax1, 1));
        rmax1 = fmaxf(rmax1, __shfl_xor_sync(0xffffffffu, rmax1, 2));

        float mn0 = fmaxf(m0, rmax0), mn1 = fmaxf(m1, rmax1);
        float cr0 = ex2f(m0 - mn0), cr1 = ex2f(m1 - mn1);
        m0 = mn0; m1 = mn1;

        uint32_t ph0[8], ph1[8];
        float rs0 = 0.f, rs1 = 0.f;
#pragma unroll
        for (int nt = 0; nt < 8; ++nt) {
            float p00 = ex2f(sacc[nt][0] - mn0);
            float p01 = ex2f(sacc[nt][1] - mn0);
            float p10 = ex2f(sacc[nt][2] - mn1);
            float p11 = ex2f(sacc[nt][3] - mn1);
            __half2 h0 = __floats2half2_rn(p00, p01);
            __half2 h1 = __floats2half2_rn(p10, p11);
            float2 f0 = __half22float2(h0);
            float2 f1 = __half22float2(h1);
            rs0 += f0.x + f0.y;
            rs1 += f1.x + f1.y;
            ph0[nt] = h2bits(h0);
            ph1[nt] = h2bits(h1);
        }
        rs0 += __shfl_xor_sync(0xffffffffu, rs0, 1);
        rs0 += __shfl_xor_sync(0xffffffffu, rs0, 2);
        rs1 += __shfl_xor_sync(0xffffffffu, rs1, 1);
        rs1 += __shfl_xor_sync(0xffffffffu, rs1, 2);
        l0 = l0 * cr0 + rs0;
        l1 = l1 * cr1 + rs1;

#pragma unroll
        for (int nt = 0; nt < 8; ++nt) {
            oacc[nt][0] *= cr0; oacc[nt][1] *= cr0;
            oacc[nt][2] *= cr1; oacc[nt][3] *= cr1;
        }

        if (has_next) STS_V(buf ^ 1);

#pragma unroll
        for (int ks = 0; ks < 4; ++ks) {
            uint32_t pa[4];
            pa[0] = ph0[2*ks    ];
            pa[1] = ph1[2*ks    ];
            pa[2] = ph0[2*ks + 1];
            pa[3] = ph1[2*ks + 1];
#pragma unroll
            for (int nt = 0; nt < 8; ++nt) {
                uint32_t bf[2];
                bf[0] = Vs2[buf*32 + ks*8 + lc    ][nt*8 + lr];
                bf[1] = Vs2[buf*32 + ks*8 + lc + 4][nt*8 + lr];
                mma_f16(oacc[nt], pa, bf, oacc[nt]);
            }
        }
    }

    float inv0 = 1.f / l0, inv1 = 1.f / l1;
#pragma unroll
    for (int nt = 0; nt < 8; ++nt) {
        int col = hoff + nt*8 + 2*lc;
        *reinterpret_cast<uint32_t*>(Og + (rb + q0 + w*16 + lr    ) * 128 + col) =
            f2h2(oacc[nt][0] * inv0, oacc[nt][1] * inv0);
        *reinterpret_cast<uint32_t*>(Og + (rb + q0 + w*16 + lr + 8) * 128 + col) =
            f2h2(oacc[nt][2] * inv1, oacc[nt][3] * inv1);
    }
#undef CP_K
#undef LDG_V
#undef STS_V
}

// ---------------- final classifier ----------------
__global__ __launch_bounds__(256) void final_kernel(
    const __half* __restrict__ hp, const float* __restrict__ W,
    const float* __restrict__ bias, float* __restrict__ out)
{
    __shared__ float Ws[256];
    __shared__ float bs[2];
    if (threadIdx.x < 256) Ws[threadIdx.x] = W[threadIdx.x];
    if (threadIdx.x < 2)   bs[threadIdx.x] = bias[threadIdx.x];
    __syncthreads();
    size_t row = (size_t)blockIdx.x * blockDim.x + threadIdx.x;
    const __half2* hr = reinterpret_cast<const __half2*>(hp + row * 128);
    float a0 = bs[0], a1 = bs[1];
#pragma unroll
    for (int k2 = 0; k2 < 64; ++k2) {
        float2 f = __half22float2(hr[k2]);
        a0 += f.x * Ws[4*k2+0] + f.y * Ws[4*k2+2];
        a1 += f.x * Ws[4*k2+1] + f.y * Ws[4*k2+3];
    }
    out[row*2+0] = a0;
    out[row*2+1] = a1;
}

// ---------------- launch ----------------
extern "C" void kernel_launch(void* const* d_in, const int* in_sizes, int n_in,
                              void* d_out, int out_size) {
    const float* X     = (const float*)d_in[0];
    const float* A     = (const float*)d_in[1];
    const float* T     = (const float*)d_in[2];
    const float* theta = (const float*)d_in[3];
    const float* W_raw = (const float*)d_in[4];
    const float* b_raw = (const float*)d_in[5];
    const float* Wd0   = (const float*)d_in[6];
    const float* bd0   = (const float*)d_in[7];
    const float* Wd1   = (const float*)d_in[8];
    const float* bd1   = (const float*)d_in[9];
    const float* W_fin = (const float*)d_in[10];
    const float* b_fin = (const float*)d_in[11];
    const float* Wq0 = (const float*)d_in[12]; const float* bq0 = (const float*)d_in[13];
    const float* Wk0 = (const float*)d_in[14]; const float* bk0 = (const float*)d_in[15];
    const float* Wv0 = (const float*)d_in[16]; const float* bv0 = (const float*)d_in[17];
    const float* Wo0 = (const float*)d_in[18]; const float* bo0 = (const float*)d_in[19];
    const float* Wq1 = (const float*)d_in[20]; const float* bq1 = (const float*)d_in[21];
    const float* Wk1 = (const float*)d_in[22]; const float* bk1 = (const float*)d_in[23];
    const float* Wv1 = (const float*)d_in[24]; const float* bv1 = (const float*)d_in[25];
    const float* Wo1 = (const float*)d_in[26]; const float* bo1 = (const float*)d_in[27];

    float* Qm;
    __half *X16, *hp, *h, *h2, *qb, *kb, *vb, *ctx;
    __half2* W16;
    cudaGetSymbolAddress((void**)&Qm,  g_Q);
    cudaGetSymbolAddress((void**)&X16, g_X16);
    cudaGetSymbolAddress((void**)&hp,  g_hp);
    cudaGetSymbolAddress((void**)&h,   g_h);
    cudaGetSymbolAddress((void**)&h2,  g_h2);
    cudaGetSymbolAddress((void**)&qb,  g_qb);
    cudaGetSymbolAddress((void**)&kb,  g_kb);
    cudaGetSymbolAddress((void**)&vb,  g_vb);
    cudaGetSymbolAddress((void**)&ctx, g_ctx);
    cudaGetSymbolAddress((void**)&W16, g_W16);

    const int attn_smem  = (256*36 + 128*36 + 64*72) * (int)sizeof(uint32_t); // 73728
    const int diff64_sm  = (5120 + 4352 + 128*36) * (int)sizeof(uint32_t);    // 56320
    const int diff128_sm = (5120 + 4352 + 128*68) * (int)sizeof(uint32_t);    // 72704
    cudaFuncSetAttribute(attn_mma_kernel,
        cudaFuncAttributeMaxDynamicSharedMemorySize, attn_smem);
    cudaFuncSetAttribute(diff_fused_kernel<64>,
        cudaFuncAttributeMaxDynamicSharedMemorySize, diff64_sm);
    cudaFuncSetAttribute(diff_fused_kernel<128>,
        cudaFuncAttributeMaxDynamicSharedMemorySize, diff128_sm);

    const int ggrid = M_ROWS / 128;
    dim3 dgrid(NNODE / 128, 1, NB);
    dim3 qkv_grid(ggrid, 3);
    dim3 attn_grid(NNODE / 256, 2, NB);

    qmix_kernel<<<2 * 1024 * 1024 / 256, 256>>>(T, theta);
    tohalf_kernel<<<M_ROWS * 64 / 1024, 256>>>(X, X16);
    wconv_kernel<<<dim3(64, 11), 256>>>(W_raw, Wd0, Wd1,
                                        Wq0, Wk0, Wv0, Wo0,
                                        Wq1, Wk1, Wv1, Wo1);

    // raw projection: hp = X @ W_raw + b_raw
    hgemm_kernel<<<ggrid, 256>>>(X16, X16, 64, 64, W16 + OFF_RAW, b_raw, nullptr, hp, 0);

    // layer 0: fused mask+diffusion+linear, then attention block
    diff_fused_kernel<64><<<dgrid, 256, diff64_sm>>>(Qm, A, X16, W16 + OFF_D0, bd0, h);
    qkv3_kernel<<<qkv_grid, 256>>>(h, hp, W16 + OFF_Q0, W16 + OFF_K0, W16 + OFF_V0,
                                   bq0, bk0, bv0, qb, kb, vb);
    attn_mma_kernel<<<attn_grid, 512, attn_smem>>>(qb, kb, vb, ctx);
    hgemm_kernel<<<ggrid, 256>>>(ctx, ctx, 128, 128, W16 + OFF_O0, bo0, nullptr, hp, 1);

    // layer 1 (no aliasing: diff writes h2)
    diff_fused_kernel<128><<<dgrid, 256, diff128_sm>>>(Qm + NN2, A, h, W16 + OFF_D1, bd1, h2);
    qkv3_kernel<<<qkv_grid, 256>>>(h2, hp, W16 + OFF_Q1, W16 + OFF_K1, W16 + OFF_V1,
                                   bq1, bk1, bv1, qb, kb, vb);
    attn_mma_kernel<<<attn_grid, 512, attn_smem>>>(qb, kb, vb, ctx);
    hgemm_kernel<<<ggrid, 256>>>(ctx, ctx, 128, 128, W16 + OFF_O1, bo1, hp, hp, 1);

    // classifier
    final_kernel<<<M_ROWS / 256, 256>>>(hp, W_fin, b_fin, (float*)d_out);
}

// round 14
// speedup vs baseline: 1.0152x; 1.0152x over previous
#include <cuda_runtime.h>
#include <cuda_fp16.h>
#include <math.h>
#include <stdint.h>

#define M_ROWS 32768          // B*N
#define NB 32
#define NNODE 1024
#define NN2 (1024u * 1024u)

// weight offsets in g_W16 (half2 units); layout [k2][128] interleaved
#define OFF_RAW 0
#define OFF_D0  4096
#define OFF_D1  8192
#define OFF_Q0  16384
#define OFF_K0  32768
#define OFF_V0  49152
#define OFF_O0  65536
#define OFF_Q1  73728
#define OFF_K1  90112
#define OFF_V1  106496
#define OFF_O1  122880

// ---------------- scratch (device globals, allocation-free) ----------------
__device__ __half2 g_W16[131072];
__device__ __half  g_P0[(size_t)NB * NN2];
__device__ __half  g_P1[(size_t)NB * NN2];
__device__ __half  g_X16[(size_t)M_ROWS * 64];
__device__ __half  g_hp [(size_t)M_ROWS * 128];
__device__ __half  g_h  [(size_t)M_ROWS * 128];
__device__ __half  g_h2 [(size_t)M_ROWS * 128];
__device__ __half  g_qb [(size_t)M_ROWS * 128];
__device__ __half  g_kb [(size_t)M_ROWS * 128];
__device__ __half  g_vb [(size_t)M_ROWS * 128];
__device__ __half  g_ctx[(size_t)M_ROWS * 128];

// ---------------- helpers ----------------
__device__ __forceinline__ uint32_t f2h2(float a, float b) {
    __half2 h = __floats2half2_rn(a, b);
    return *reinterpret_cast<uint32_t*>(&h);
}
__device__ __forceinline__ uint32_t h2bits(__half2 h) {
    return *reinterpret_cast<uint32_t*>(&h);
}
__device__ __forceinline__ float ex2f(float x) {
    float r;
    asm("ex2.approx.ftz.f32 %0, %1;" : "=f"(r) : "f"(x));
    return r;
}
__device__ __forceinline__ void cp16(uint32_t dst_smem, const void* src) {
    asm volatile("cp.async.ca.shared.global [%0], [%1], 16;\n"
                 :: "r"(dst_smem), "l"(src));
}
__device__ __forceinline__ void cp_commit() {
    asm volatile("cp.async.commit_group;\n");
}
__device__ __forceinline__ void cp_wait0() {
    asm volatile("cp.async.wait_group 0;\n");
}
__device__ __forceinline__ uint32_t smem_u32(const void* p) {
    return (uint32_t)__cvta_generic_to_shared(p);
}

__device__ __forceinline__ void mma_f16(float* d, const uint32_t* a,
                                        const uint32_t* b, const float* c) {
    asm volatile(
        "mma.sync.aligned.m16n8k16.row.col.f32.f16.f16.f32 "
        "{%0,%1,%2,%3}, {%4,%5,%6,%7}, {%8,%9}, {%10,%11,%12,%13};\n"
        : "=f"(d[0]), "=f"(d[1]), "=f"(d[2]), "=f"(d[3])
        : "r"(a[0]), "r"(a[1]), "r"(a[2]), "r"(a[3]),
          "r"(b[0]), "r"(b[1]),
          "f"(c[0]), "f"(c[1]), "f"(c[2]), "f"(c[3]));
}

// ------- fused qmix+pmul: P16[l] = half((sum_k thsm[l,k]*T[l,k]) ⊙ A) -------
// T is L2-resident after batch 0 (24 MB, ij repeats per batch).
__global__ void qmixpmul_kernel(const float* __restrict__ T,
                                const float* __restrict__ th,
                                const float* __restrict__ A) {
    size_t i  = ((size_t)blockIdx.x * 256 + threadIdx.x) * 4;
    size_t ij = i & (NN2 - 1);

    // layer 0 softmax
    float a0 = th[0], b0 = th[1], c0 = th[2];
    float m0 = fmaxf(a0, fmaxf(b0, c0));
    float e0a = __expf(a0 - m0), e0b = __expf(b0 - m0), e0c = __expf(c0 - m0);
    float inv0 = 1.f / (e0a + e0b + e0c);
    // layer 1 softmax
    float a1 = th[3], b1 = th[4], c1 = th[5];
    float m1 = fmaxf(a1, fmaxf(b1, c1));
    float e1a = __expf(a1 - m1), e1b = __expf(b1 - m1), e1c = __expf(c1 - m1);
    float inv1 = 1.f / (e1a + e1b + e1c);

    float4 av  = *reinterpret_cast<const float4*>(A + i);
    float4 t00 = *reinterpret_cast<const float4*>(T + 0u*NN2 + ij);
    float4 t01 = *reinterpret_cast<const float4*>(T + 1u*NN2 + ij);
    float4 t02 = *reinterpret_cast<const float4*>(T + 2u*NN2 + ij);
    float4 t10 = *reinterpret_cast<const float4*>(T + 3u*NN2 + ij);
    float4 t11 = *reinterpret_cast<const float4*>(T + 4u*NN2 + ij);
    float4 t12 = *reinterpret_cast<const float4*>(T + 5u*NN2 + ij);

    float4 q0, q1;
    q0.x = inv0 * (e0a*t00.x + e0b*t01.x + e0c*t02.x);
    q0.y = inv0 * (e0a*t00.y + e0b*t01.y + e0c*t02.y);
    q0.z = inv0 * (e0a*t00.z + e0b*t01.z + e0c*t02.z);
    q0.w = inv0 * (e0a*t00.w + e0b*t01.w + e0c*t02.w);
    q1.x = inv1 * (e1a*t10.x + e1b*t11.x + e1c*t12.x);
    q1.y = inv1 * (e1a*t10.y + e1b*t11.y + e1c*t12.y);
    q1.z = inv1 * (e1a*t10.z + e1b*t11.z + e1c*t12.z);
    q1.w = inv1 * (e1a*t10.w + e1b*t11.w + e1c*t12.w);

    uint2 u0, u1;
    u0.x = f2h2(q0.x*av.x, q0.y*av.y);
    u0.y = f2h2(q0.z*av.z, q0.w*av.w);
    u1.x = f2h2(q1.x*av.x, q1.y*av.y);
    u1.y = f2h2(q1.z*av.z, q1.w*av.w);
    *reinterpret_cast<uint2*>(g_P0 + i) = u0;
    *reinterpret_cast<uint2*>(g_P1 + i) = u1;
}

// ---------------- fp32 -> fp16 cast (for X) ----------------
__global__ void tohalf_kernel(const float* __restrict__ x, __half* __restrict__ o) {
    size_t i = ((size_t)blockIdx.x * 256 + threadIdx.x) * 4;
    float4 v = *reinterpret_cast<const float4*>(x + i);
    uint2 u;
    u.x = f2h2(v.x, v.y);
    u.y = f2h2(v.z, v.w);
    *reinterpret_cast<uint2*>(o + i) = u;
}

// ------- weight convert + interleave -------
__global__ void wconv_kernel(
    const float* r,  const float* d0, const float* d1,
    const float* q0, const float* k0, const float* v0, const float* o0,
    const float* q1, const float* k1, const float* v1, const float* o1)
{
    const float* srcs[11] = {r, d0, d1, q0, k0, v0, o0, q1, k1, v1, o1};
    const int    Ks[11]   = {64, 64, 128, 256, 256, 256, 128, 256, 256, 256, 128};
    const int    offs[11] = {OFF_RAW, OFF_D0, OFF_D1, OFF_Q0, OFF_K0, OFF_V0,
                             OFF_O0, OFF_Q1, OFF_K1, OFF_V1, OFF_O1};
    int m   = blockIdx.y;
    int idx = blockIdx.x * 256 + threadIdx.x;
    int K   = Ks[m];
    if (idx >= K * 64) return;
    const float* s = srcs[m];
    int k2 = idx >> 7, n = idx & 127;
    g_W16[offs[m] + idx] =
        __floats2half2_rn(s[(2*k2)*128 + n], s[(2*k2 + 1)*128 + n]);
}

// ---------- shared GEMM body (device function) ----------
struct GemmSmem {
    uint32_t As[2][128][20];
    uint32_t Bs[2][16][136];
};

__device__ __forceinline__ void hgemm_body(
    GemmSmem* sm,
    const __half* A1, const __half* A2, int K1, int K,
    const __half2* W2, const float* bias,
    const __half* base, __half* C, int relu, int row0)
{
    const int tid  = threadIdx.x;
    const int lane = tid & 31;
    const int w    = tid >> 5;
    const int wm   = w & 3;
    const int wn   = w >> 2;
    const int lr   = lane >> 2;
    const int lc   = lane & 3;
    const int sa_r   = tid >> 1;
    const int sa_k16 = (tid & 1) << 4;

#define CP_A(k0, bufi)                                                         \
    {                                                                          \
        int kg = (k0) + sa_k16;                                                \
        const __half* src = (kg < K1) ? A1 : A2;                               \
        int kk     = (kg < K1) ? kg : (kg - K1);                               \
        int stride = (kg < K1) ? K1 : (K - K1);                                \
        const __half* p = src + (size_t)(row0 + sa_r) * stride + kk;           \
        uint32_t d = smem_u32(&sm->As[bufi][sa_r][sa_k16 >> 1]);               \
        cp16(d, p);                                                            \
        cp16(d + 16, p + 8);                                                   \
    }

#define CP_B(k0, bufi)                                                         \
    {                                                                          \
        _Pragma("unroll")                                                      \
        for (int i = 0; i < 2; ++i) {                                          \
            int idx = tid + i * 256;                                           \
            int k2r = idx >> 5, nq = (idx & 31) << 2;                          \
            cp16(smem_u32(&sm->Bs[bufi][k2r][nq]),                             \
                 W2 + (size_t)(((k0) >> 1) + k2r) * 128 + nq);                 \
        }                                                                      \
    }

    float acc[2][8][4];
#pragma unroll
    for (int mt = 0; mt < 2; ++mt)
#pragma unroll
        for (int nt = 0; nt < 8; ++nt)
#pragma unroll
            for (int i = 0; i < 4; ++i) acc[mt][nt][i] = 0.f;

    CP_A(0, 0);
    CP_B(0, 0);
    cp_commit();

    int buf = 0;
    for (int k0 = 0; k0 < K; k0 += 32) {
        cp_wait0();
        __syncthreads();
        const bool has_next = (k0 + 32 < K);
        if (has_next) {
            CP_A(k0 + 32, buf ^ 1);
            CP_B(k0 + 32, buf ^ 1);
            cp_commit();
        }
#pragma unroll
        for (int s = 0; s < 2; ++s) {
            uint32_t a[2][4], b[8][2];
#pragma unroll
            for (int mt = 0; mt < 2; ++mt) {
                int rm = wm*32 + mt*16 + lr;
                a[mt][0] = sm->As[buf][rm    ][s*8 + lc    ];
                a[mt][1] = sm->As[buf][rm + 8][s*8 + lc    ];
                a[mt][2] = sm->As[buf][rm    ][s*8 + lc + 4];
                a[mt][3] = sm->As[buf][rm + 8][s*8 + lc + 4];
            }
#pragma unroll
            for (int nt = 0; nt < 8; ++nt) {
                int nb = wn*64 + nt*8 + lr;
                b[nt][0] = sm->Bs[buf][s*8 + lc    ][nb];
                b[nt][1] = sm->Bs[buf][s*8 + lc + 4][nb];
            }
#pragma unroll
            for (int mt = 0; mt < 2; ++mt)
#pragma unroll
                for (int nt = 0; nt < 8; ++nt)
                    mma_f16(acc[mt][nt], a[mt], b[nt], acc[mt][nt]);
        }
        buf ^= 1;
    }

#pragma unroll
    for (int mt = 0; mt < 2; ++mt) {
#pragma unroll
        for (int nt = 0; nt < 8; ++nt) {
            int col = wn*64 + nt*8 + 2*lc;
            float b0 = bias[col], b1 = bias[col+1];
#pragma unroll
            for (int half = 0; half < 2; ++half) {
                int row = row0 + wm*32 + mt*16 + lr + half*8;
                float v0 = acc[mt][nt][half*2+0] + b0;
                float v1 = acc[mt][nt][half*2+1] + b1;
                if (relu) { v0 = fmaxf(v0, 0.f); v1 = fmaxf(v1, 0.f); }
                if (base) {
                    __half2 bh = *reinterpret_cast<const __half2*>(
                        base + (size_t)row * 128 + col);
                    float2 bf = __half22float2(bh);
                    v0 += bf.x; v1 += bf.y;
                }
                *reinterpret_cast<uint32_t*>(C + (size_t)row * 128 + col) =
                    f2h2(v0, v1);
            }
        }
    }
#undef CP_A
#undef CP_B
}

__global__ __launch_bounds__(256) void hgemm_kernel(
    const __half* __restrict__ A1, const __half* __restrict__ A2, int K1, int K,
    const __half2* __restrict__ W2, const float* __restrict__ bias,
    const __half* __restrict__ base, __half* __restrict__ C, int relu)
{
    __shared__ GemmSmem sm;
    hgemm_body(&sm, A1, A2, K1, K, W2, bias, base, C, relu, blockIdx.x << 7);
}

// batched q/k/v: blockIdx.y selects the matrix
__global__ __launch_bounds__(256) void qkv3_kernel(
    const __half* __restrict__ A1, const __half* __restrict__ A2,
    const __half2* __restrict__ Wq, const __half2* __restrict__ Wk,
    const __half2* __restrict__ Wv,
    const float* __restrict__ bq, const float* __restrict__ bk,
    const float* __restrict__ bv,
    __half* __restrict__ Oq, __half* __restrict__ Ok, __half* __restrict__ Ov)
{
    __shared__ GemmSmem sm;
    const int m = blockIdx.y;
    const __half2* W2 = (m == 0) ? Wq : (m == 1) ? Wk : Wv;
    const float* bias = (m == 0) ? bq : (m == 1) ? bk : bv;
    __half* C         = (m == 0) ? Oq : (m == 1) ? Ok : Ov;
    hgemm_body(&sm, A1, A2, 128, 256, W2, bias, nullptr, C, 0, blockIdx.x << 7);
}

// ====== fused diffusion + linear: Hout = relu((P16 @ Hin) @ Wd + bias) ======
template<int BN>
__global__ __launch_bounds__(256) void diff_fused_kernel(
    const __half* __restrict__ P, const __half* __restrict__ Hin,
    const __half2* __restrict__ Wd2, const float* __restrict__ bias,
    __half* __restrict__ Hout)
{
    constexpr int WN = BN / 2;
    constexpr int NT = WN / 8;
    constexpr int ZW = BN / 2 + 4;

    extern __shared__ uint32_t dsm[];
    uint32_t* AS = dsm;                    // [2][128][20]
    uint32_t* BS = dsm + 5120;             // [2][16][136]
    uint32_t* ZS = dsm + 5120 + 4352;      // [128][ZW]
#define ASX(bufi, r, c) AS[(bufi)*2560 + (r)*20 + (c)]
#define BSX(bufi, r, c) BS[(bufi)*2176 + (r)*136 + (c)]
#define ZSX(r, c)       ZS[(r)*ZW + (c)]

    const int tid  = threadIdx.x;
    const int lane = tid & 31;
    const int w    = tid >> 5;
    const int wm   = w & 3;
    const int wn   = w >> 2;
    const int lr   = lane >> 2;
    const int lc   = lane & 3;
    const int b    = blockIdx.z;
    const int i0   = blockIdx.x << 7;
    const size_t pb = (size_t)b * NN2;
    const size_t hb = (size_t)b * NNODE * BN;

    const int sa_r   = tid >> 1;
    const int sa_k16 = (tid & 1) << 4;

    uint4 bu0, bu1;

#define CP_P(j0, bufi)                                                         \
    {                                                                          \
        const __half* p = P + pb + (size_t)(i0 + sa_r) * NNODE + (j0) + sa_k16;\
        uint32_t d = smem_u32(&ASX(bufi, sa_r, sa_k16 >> 1));                  \
        cp16(d, p);                                                            \
        cp16(d + 16, p + 8);                                                   \
    }

#define DIFF_LDG_B(j0)                                                         \
    {                                                                          \
        if (BN == 128) {                                                       \
            int k2r = tid >> 4, nh = (tid & 15) * 8;                           \
            const __half* q = Hin + hb + (size_t)((j0) + 2*k2r) * BN + nh;     \
            bu0 = *reinterpret_cast<const uint4*>(q);                          \
            bu1 = *reinterpret_cast<const uint4*>(q + BN);                     \
        } else {                                                               \
            int k2r = tid >> 4, nh = (tid & 15) * 4;                           \
            const __half* q = Hin + hb + (size_t)((j0) + 2*k2r) * BN + nh;     \
            uint2 t0 = *reinterpret_cast<const uint2*>(q);                     \
            uint2 t1 = *reinterpret_cast<const uint2*>(q + BN);                \
            bu0.x = t0.x; bu0.y = t0.y; bu1.x = t1.x; bu1.y = t1.y;            \
        }                                                                      \
    }

#define DIFF_STS_B(bufi)                                                       \
    {                                                                          \
        if (BN == 128) {                                                       \
            int k2r = tid >> 4, nh = (tid & 15) * 8;                           \
            uint4 v0, v1;                                                      \
            v0.x = __byte_perm(bu0.x, bu1.x, 0x5410);                          \
            v0.y = __byte_perm(bu0.x, bu1.x, 0x7632);                          \
            v0.z = __byte_perm(bu0.y, bu1.y, 0x5410);                          \
            v0.w = __byte_perm(bu0.y, bu1.y, 0x7632);                          \
            v1.x = __byte_perm(bu0.z, bu1.z, 0x5410);                          \
            v1.y = __byte_perm(bu0.z, bu1.z, 0x7632);                          \
            v1.z = __byte_perm(bu0.w, bu1.w, 0x5410);                          \
            v1.w = __byte_perm(bu0.w, bu1.w, 0x7632);                          \
            *reinterpret_cast<uint4*>(&BSX(bufi, k2r, nh    )) = v0;           \
            *reinterpret_cast<uint4*>(&BSX(bufi, k2r, nh + 4)) = v1;           \
        } else {                                                               \
            int k2r = tid >> 4, nh = (tid & 15) * 4;                           \
            uint4 v0;                                                          \
            v0.x = __byte_perm(bu0.x, bu1.x, 0x5410);                          \
            v0.y = __byte_perm(bu0.x, bu1.x, 0x7632);                          \
            v0.z = __byte_perm(bu0.y, bu1.y, 0x5410);                          \
            v0.w = __byte_perm(bu0.y, bu1.y, 0x7632);                          \
            *reinterpret_cast<uint4*>(&BSX(bufi, k2r, nh)) = v0;               \
        }                                                                      \
    }

    // ---------------- phase 1: z = P @ Hin ----------------
    float acc[2][NT][4];
#pragma unroll
    for (int mt = 0; mt < 2; ++mt)
#pragma unroll
        for (int nt = 0; nt < NT; ++nt)
#pragma unroll
            for (int i = 0; i < 4; ++i) acc[mt][nt][i] = 0.f;

    DIFF_LDG_B(0);
    CP_P(0, 0);
    cp_commit();
    DIFF_STS_B(0);

    int buf = 0;
    for (int j0 = 0; j0 < NNODE; j0 += 32) {
        cp_wait0();
        __syncthreads();
        const bool has_next = (j0 + 32 < NNODE);
        if (has_next) {
            CP_P(j0 + 32, buf ^ 1);
            cp_commit();
            DIFF_LDG_B(j0 + 32);
        }
#pragma unroll
        for (int s = 0; s < 2; ++s) {
            uint32_t a[2][4], bf[NT][2];
#pragma unroll
            for (int mt = 0; mt < 2; ++mt) {
                int rm = wm*32 + mt*16 + lr;
                a[mt][0] = ASX(buf, rm    , s*8 + lc    );
                a[mt][1] = ASX(buf, rm + 8, s*8 + lc    );
                a[mt][2] = ASX(buf, rm    , s*8 + lc + 4);
                a[mt][3] = ASX(buf, rm + 8, s*8 + lc + 4);
            }
#pragma unroll
            for (int nt = 0; nt < NT; ++nt) {
                int nb = wn*WN + nt*8 + lr;
                bf[nt][0] = BSX(buf, s*8 + lc    , nb);
                bf[nt][1] = BSX(buf, s*8 + lc + 4, nb);
            }
#pragma unroll
            for (int mt = 0; mt < 2; ++mt)
#pragma unroll
                for (int nt = 0; nt < NT; ++nt)
                    mma_f16(acc[mt][nt], a[mt], bf[nt], acc[mt][nt]);
        }
        if (has_next) DIFF_STS_B(buf ^ 1);
        buf ^= 1;
    }

#pragma unroll
    for (int mt = 0; mt < 2; ++mt) {
#pragma unroll
        for (int nt = 0; nt < NT; ++nt) {
            int col = wn*WN + nt*8 + 2*lc;
#pragma unroll
            for (int half = 0; half < 2; ++half) {
                int row = wm*32 + mt*16 + lr + half*8;
                ZSX(row, col >> 1) =
                    f2h2(acc[mt][nt][half*2+0], acc[mt][nt][half*2+1]);
            }
        }
    }
    __syncthreads();

    // ---------------- phase 2: Hout = relu(z @ Wd + bias) ----------------
#define CP_W(k0, bufi)                                                         \
    {                                                                          \
        _Pragma("unroll")                                                      \
        for (int i = 0; i < 2; ++i) {                                          \
            int idx = tid + i * 256;                                           \
            int k2r = idx >> 5, nq = (idx & 31) << 2;                          \
            cp16(smem_u32(&BSX(bufi, k2r, nq)),                                \
                 Wd2 + (size_t)(((k0) >> 1) + k2r) * 128 + nq);                \
        }                                                                      \
    }

    float acc2[2][8][4];
#pragma unroll
    for (int mt = 0; mt < 2; ++mt)
#pragma unroll
        for (int nt = 0; nt < 8; ++nt)
#pragma unroll
            for (int i = 0; i < 4; ++i) acc2[mt][nt][i] = 0.f;

    CP_W(0, 0);
    cp_commit();

    buf = 0;
    for (int k0 = 0; k0 < BN; k0 += 32) {
        cp_wait0();
        __syncthreads();
        const bool has_next = (k0 + 32 < BN);
        if (has_next) {
            CP_W(k0 + 32, buf ^ 1);
            cp_commit();
        }
        const int k2b = k0 >> 1;
#pragma unroll
        for (int s = 0; s < 2; ++s) {
            uint32_t a[2][4], bfr[8][2];
#pragma unroll
            for (int mt = 0; mt < 2; ++mt) {
                int rm = wm*32 + mt*16 + lr;
                a[mt][0] = ZSX(rm    , k2b + s*8 + lc    );
                a[mt][1] = ZSX(rm + 8, k2b + s*8 + lc    );
                a[mt][2] = ZSX(rm    , k2b + s*8 + lc + 4);
                a[mt][3] = ZSX(rm + 8, k2b + s*8 + lc + 4);
            }
#pragma unroll
            for (int nt = 0; nt < 8; ++nt) {
                int nb = wn*64 + nt*8 + lr;
                bfr[nt][0] = BSX(buf, s*8 + lc    , nb);
                bfr[nt][1] = BSX(buf, s*8 + lc + 4, nb);
            }
#pragma unroll
            for (int mt = 0; mt < 2; ++mt)
#pragma unroll
                for (int nt = 0; nt < 8; ++nt)
                    mma_f16(acc2[mt][nt], a[mt], bfr[nt], acc2[mt][nt]);
        }
        buf ^= 1;
    }

#pragma unroll
    for (int mt = 0; mt < 2; ++mt) {
#pragma unroll
        for (int nt = 0; nt < 8; ++nt) {
            int col = wn*64 + nt*8 + 2*lc;
            float b0 = bias[col], b1 = bias[col+1];
#pragma unroll
            for (int half = 0; half < 2; ++half) {
                int row = i0 + wm*32 + mt*16 + lr + half*8;
                float v0 = fmaxf(acc2[mt][nt][half*2+0] + b0, 0.f);
                float v1 = fmaxf(acc2[mt][nt][half*2+1] + b1, 0.f);
                *reinterpret_cast<uint32_t*>(
                    Hout + ((size_t)b * NNODE + row) * 128 + col) = f2h2(v0, v1);
            }
        }
    }
#undef CP_P
#undef DIFF_LDG_B
#undef DIFF_STS_B
#undef CP_W
#undef ASX
#undef BSX
#undef ZSX
}

// ========== fp16 flash attention: 256 q / 512 thr; P register-resident ==========
__global__ __launch_bounds__(512) void attn_mma_kernel(
    const __half* __restrict__ Qg, const __half* __restrict__ Kg,
    const __half* __restrict__ Vg, __half* __restrict__ Og)
{
    extern __shared__ uint32_t asmem[];
    uint32_t (*Ps2)[36] = reinterpret_cast<uint32_t(*)[36]>(asmem);            // 256 rows (Q staging only)
    uint32_t (*Ks2)[36] = reinterpret_cast<uint32_t(*)[36]>(asmem + 256*36);   // 2*64 rows
    uint32_t (*Vs2)[72] = reinterpret_cast<uint32_t(*)[72]>(asmem + 384*36);   // 2*32 rows

    const int tid  = threadIdx.x;
    const int lane = tid & 31;
    const int w    = tid >> 5;
    const int lr   = lane >> 2;
    const int lc   = lane & 3;
    const int b    = blockIdx.z, h = blockIdx.y;
    const int q0   = blockIdx.x << 8;
    const size_t rb = (size_t)b * NNODE;
    const int hoff = h * 64;
    const float SC = 0.125f * 1.4426950408889634f;
    const __half2 h2sc = __float2half2_rn(SC);

    {
        int r   = w*16 + (lane >> 1);
        int seg = (lane & 1) * 32;
        const __half* p = Qg + (rb + q0 + r) * 128 + hoff + seg;
#pragma unroll
        for (int jj = 0; jj < 4; ++jj) {
            uint4 u = *reinterpret_cast<const uint4*>(p + 8*jj);
            *reinterpret_cast<uint4*>(&Ps2[r][(seg>>1) + 4*jj]) = u;
        }
    }
    __syncwarp();

    uint32_t qa[4][4];
#pragma unroll
    for (int ks = 0; ks < 4; ++ks) {
        qa[ks][0] = Ps2[w*16 + lr    ][ks*8 + lc    ];
        qa[ks][1] = Ps2[w*16 + lr + 8][ks*8 + lc    ];
        qa[ks][2] = Ps2[w*16 + lr    ][ks*8 + lc + 4];
        qa[ks][3] = Ps2[w*16 + lr + 8][ks*8 + lc + 4];
#pragma unroll
        for (int i = 0; i < 4; ++i) {
            __half2 hv = *reinterpret_cast<__half2*>(&qa[ks][i]);
            hv = __hmul2(hv, h2sc);
            qa[ks][i] = h2bits(hv);
        }
    }

    float m0 = -1e30f, m1 = -1e30f, l0 = 0.f, l1 = 0.f;
    float oacc[8][4];
#pragma unroll
    for (int nt = 0; nt < 8; ++nt)
#pragma unroll
        for (int i = 0; i < 4; ++i) oacc[nt][i] = 0.f;

    uint2 uv0, uv1;
    const int kr   = tid >> 3;
    const int kseg = (tid & 7) << 3;
    const int vk2r = tid >> 4;
    const int vdq  = (tid & 15) * 4;

#define CP_K(j0, bufi)                                                         \
    {                                                                          \
        const __half* p = Kg + (rb + (j0) + kr) * 128 + hoff + kseg;           \
        cp16(smem_u32(&Ks2[(bufi)*64 + kr][kseg >> 1]), p);                    \
    }

#define LDG_V(j0)                                                              \
    {                                                                          \
        const __half* q = Vg + (rb + (j0) + 2*vk2r) * 128 + hoff + vdq;        \
        uv0 = *reinterpret_cast<const uint2*>(q);                              \
        uv1 = *reinterpret_cast<const uint2*>(q + 128);                        \
    }

#define STS_V(bufi)                                                            \
    {                                                                          \
        uint4 v0;                                                              \
        v0.x = __byte_perm(uv0.x, uv1.x, 0x5410);                              \
        v0.y = __byte_perm(uv0.x, uv1.x, 0x7632);                              \
        v0.z = __byte_perm(uv0.y, uv1.y, 0x5410);                              \
        v0.w = __byte_perm(uv0.y, uv1.y, 0x7632);                              \
        *reinterpret_cast<uint4*>(&Vs2[(bufi)*32 + vk2r][vdq]) = v0;           \
    }

    CP_K(0, 0);
    cp_commit();
    LDG_V(0);
    STS_V(0);

    for (int c = 0; c < NNODE/64; ++c) {
        const int buf = c & 1;
        cp_wait0();
        __syncthreads();

        const bool has_next = (c + 1 < NNODE/64);
        if (has_next) {
            CP_K((c + 1) * 64, buf ^ 1);
            cp_commit();
            LDG_V((c + 1) * 64);
        }

        float sacc[8][4];
#pragma unroll
        for (int nt = 0; nt < 8; ++nt)
#pragma unroll
            for (int i = 0; i < 4; ++i) sacc[nt][i] = 0.f;
#pragma unroll
        for (int ks = 0; ks < 4; ++ks) {
#pragma unroll
            for (int nt = 0; nt < 8; ++nt) {
                uint32_t bf[2];
                bf[0] = Ks2[buf*64 + nt*8 + lr][ks*8 + lc    ];
                bf[1] = Ks2[buf*64 + nt*8 + lr][ks*8 + lc + 4];
                mma_f16(sacc[nt], qa[ks], bf, sacc[nt]);
            }
        }

        float rmax0 = -1e30f, rmax1 = -1e30f;
#pragma unroll
        for (int nt = 0; nt < 8; ++nt) {
            rmax0 = fmaxf(rmax0, fmaxf(sacc[nt][0], sacc[nt][1]));
            rmax1 = fmaxf(rmax1, fmaxf(sacc[nt][2], sacc[nt][3]));
        }
        rmax0 = fmaxf(rmax0, __shfl_xor_sync(0xffffffffu, rmax0, 1));
        rmax0 = fmaxf(rmax0, __shfl_xor_sync(0xffffffffu, rmax0, 2));
        rmax1 = fmaxf(rmax1, __shfl_xor_sync(0xffffffffu, rmax1, 1));
        rmax1 = fmaxf(rmax1, __shfl_xor_sync(0xffffffffu, rmax1, 2));

        float mn0 = fmaxf(m0, rmax0), mn1 = fmaxf(m1, rmax1);
        float cr0 = ex2f(m0 - mn0), cr1 = ex2f(m1 - mn1);
        m0 = mn0; m1 = mn1;

        uint32_t ph0[8], ph1[8];
        float rs0 = 0.f, rs1 = 0.f;
#pragma unroll
        for (int nt = 0; nt < 8; ++nt) {
            float p00 = ex2f(sacc[nt][0] - mn0);
            float p01 = ex2f(sacc[nt][1] - mn0);
            float p10 = ex2f(sacc[nt][2] - mn1);
            float p11 = ex2f(sacc[nt][3] - mn1);
            __half2 h0 = __floats2half2_rn(p00, p01);
            __half2 h1 = __floats2half2_rn(p10, p11);
            float2 f0 = __half22float2(h0);
            float2 f1 = __half22float2(h1);
            rs0 += f0.x + f0.y;
            rs1 += f1.x + f1.y;
            ph0[nt] = h2bits(h0);
            ph1[nt] = h2bits(h1);
        }
        rs0 += __shfl_xor_sync(0xffffffffu, rs0, 1);
        rs0 += __shfl_xor_sync(0xffffffffu, rs0, 2);
        rs1 += __shfl_xor_sync(0xffffffffu, rs1, 1);
        rs1 += __shfl_xor_sync(0xffffffffu, rs1, 2);
        l0 = l0 * cr0 + rs0;
        l1 = l1 * cr1 + rs1;

#pragma unroll
        for (int nt = 0; nt < 8; ++nt) {
            oacc[nt][0] *= cr0; oacc[nt][1] *= cr0;
            oacc[nt][2] *= cr1; oacc[nt][3] *= cr1;
        }

        if (has_next) STS_V(buf ^ 1);

#pragma unroll
        for (int ks = 0; ks < 4; ++ks) {
            uint32_t pa[4];
            pa[0] = ph0[2*ks    ];
            pa[1] = ph1[2*ks    ];
            pa[2] = ph0[2*ks + 1];
            pa[3] = ph1[2*ks + 1];
#pragma unroll
            for (int nt = 0; nt < 8; ++nt) {
                uint32_t bf[2];
                bf[0] = Vs2[buf*32 + ks*8 + lc    ][nt*8 + lr];
                bf[1] = Vs2[buf*32 + ks*8 + lc + 4][nt*8 + lr];
                mma_f16(oacc[nt], pa, bf, oacc[nt]);
            }
        }
    }

    float inv0 = 1.f / l0, inv1 = 1.f / l1;
#pragma unroll
    for (int nt = 0; nt < 8; ++nt) {
        int col = hoff + nt*8 + 2*lc;
        *reinterpret_cast<uint32_t*>(Og + (rb + q0 + w*16 + lr    ) * 128 + col) =
            f2h2(oacc[nt][0] * inv0, oacc[nt][1] * inv0);
        *reinterpret_cast<uint32_t*>(Og + (rb + q0 + w*16 + lr + 8) * 128 + col) =
            f2h2(oacc[nt][2] * inv1, oacc[nt][3] * inv1);
    }
#undef CP_K
#undef LDG_V
#undef STS_V
}

// ---------------- final classifier ----------------
__global__ __launch_bounds__(256) void final_kernel(
    const __half* __restrict__ hp, const float* __restrict__ W,
    const float* __restrict__ bias, float* __restrict__ out)
{
    __shared__ float Ws[256];
    __shared__ float bs[2];
    if (threadIdx.x < 256) Ws[threadIdx.x] = W[threadIdx.x];
    if (threadIdx.x < 2)   bs[threadIdx.x] = bias[threadIdx.x];
    __syncthreads();
    size_t row = (size_t)blockIdx.x * blockDim.x + threadIdx.x;
    const __half2* hr = reinterpret_cast<const __half2*>(hp + row * 128);
    float a0 = bs[0], a1 = bs[1];
#pragma unroll
    for (int k2 = 0; k2 < 64; ++k2) {
        float2 f = __half22float2(hr[k2]);
        a0 += f.x * Ws[4*k2+0] + f.y * Ws[4*k2+2];
        a1 += f.x * Ws[4*k2+1] + f.y * Ws[4*k2+3];
    }
    out[row*2+0] = a0;
    out[row*2+1] = a1;
}

// ---------------- launch ----------------
extern "C" void kernel_launch(void* const* d_in, const int* in_sizes, int n_in,
                              void* d_out, int out_size) {
    const float* X     = (const float*)d_in[0];
    const float* A     = (const float*)d_in[1];
    const float* T     = (const float*)d_in[2];
    const float* theta = (const float*)d_in[3];
    const float* W_raw = (const float*)d_in[4];
    const float* b_raw = (const float*)d_in[5];
    const float* Wd0   = (const float*)d_in[6];
    const float* bd0   = (const float*)d_in[7];
    const float* Wd1   = (const float*)d_in[8];
    const float* bd1   = (const float*)d_in[9];
    const float* W_fin = (const float*)d_in[10];
    const float* b_fin = (const float*)d_in[11];
    const float* Wq0 = (const float*)d_in[12]; const float* bq0 = (const float*)d_in[13];
    const float* Wk0 = (const float*)d_in[14]; const float* bk0 = (const float*)d_in[15];
    const float* Wv0 = (const float*)d_in[16]; const float* bv0 = (const float*)d_in[17];
    const float* Wo0 = (const float*)d_in[18]; const float* bo0 = (const float*)d_in[19];
    const float* Wq1 = (const float*)d_in[20]; const float* bq1 = (const float*)d_in[21];
    const float* Wk1 = (const float*)d_in[22]; const float* bk1 = (const float*)d_in[23];
    const float* Wv1 = (const float*)d_in[24]; const float* bv1 = (const float*)d_in[25];
    const float* Wo1 = (const float*)d_in[26]; const float* bo1 = (const float*)d_in[27];

    __half *P0, *P1, *X16, *hp, *h, *h2, *qb, *kb, *vb, *ctx;
    __half2* W16;
    cudaGetSymbolAddress((void**)&P0,  g_P0);
    cudaGetSymbolAddress((void**)&P1,  g_P1);
    cudaGetSymbolAddress((void**)&X16, g_X16);
    cudaGetSymbolAddress((void**)&hp,  g_hp);
    cudaGetSymbolAddress((void**)&h,   g_h);
    cudaGetSymbolAddress((void**)&h2,  g_h2);
    cudaGetSymbolAddress((void**)&qb,  g_qb);
    cudaGetSymbolAddress((void**)&kb,  g_kb);
    cudaGetSymbolAddress((void**)&vb,  g_vb);
    cudaGetSymbolAddress((void**)&ctx, g_ctx);
    cudaGetSymbolAddress((void**)&W16, g_W16);

    const int attn_smem  = (256*36 + 128*36 + 64*72) * (int)sizeof(uint32_t); // 73728
    const int diff64_sm  = (5120 + 4352 + 128*36) * (int)sizeof(uint32_t);    // 56320
    const int diff128_sm = (5120 + 4352 + 128*68) * (int)sizeof(uint32_t);    // 72704
    cudaFuncSetAttribute(attn_mma_kernel,
        cudaFuncAttributeMaxDynamicSharedMemorySize, attn_smem);
    cudaFuncSetAttribute(diff_fused_kernel<64>,
        cudaFuncAttributeMaxDynamicSharedMemorySize, diff64_sm);
    cudaFuncSetAttribute(diff_fused_kernel<128>,
        cudaFuncAttributeMaxDynamicSharedMemorySize, diff128_sm);

    const int ggrid = M_ROWS / 128;
    dim3 dgrid(NNODE / 128, 1, NB);
    dim3 qkv_grid(ggrid, 3);
    dim3 attn_grid(NNODE / 256, 2, NB);

    qmixpmul_kernel<<<NB * 1024 * 1024 / 1024, 256>>>(T, theta, A);
    tohalf_kernel<<<M_ROWS * 64 / 1024, 256>>>(X, X16);
    wconv_kernel<<<dim3(64, 11), 256>>>(W_raw, Wd0, Wd1,
                                        Wq0, Wk0, Wv0, Wo0,
                                        Wq1, Wk1, Wv1, Wo1);

    // raw projection: hp = X @ W_raw + b_raw
    hgemm_kernel<<<ggrid, 256>>>(X16, X16, 64, 64, W16 + OFF_RAW, b_raw, nullptr, hp, 0);

    // layer 0: fused diffusion+linear, then attention block
    diff_fused_kernel<64><<<dgrid, 256, diff64_sm>>>(P0, X16, W16 + OFF_D0, bd0, h);
    qkv3_kernel<<<qkv_grid, 256>>>(h, hp, W16 + OFF_Q0, W16 + OFF_K0, W16 + OFF_V0,
                                   bq0, bk0, bv0, qb, kb, vb);
    attn_mma_kernel<<<attn_grid, 512, attn_smem>>>(qb, kb, vb, ctx);
    hgemm_kernel<<<ggrid, 256>>>(ctx, ctx, 128, 128, W16 + OFF_O0, bo0, nullptr, hp, 1);

    // layer 1 (no aliasing: diff writes h2)
    diff_fused_kernel<128><<<dgrid, 256, diff128_sm>>>(P1, h, W16 + OFF_D1, bd1, h2);
    qkv3_kernel<<<qkv_grid, 256>>>(h2, hp, W16 + OFF_Q1, W16 + OFF_K1, W16 + OFF_V1,
                                   bq1, bk1, bv1, qb, kb, vb);
    attn_mma_kernel<<<attn_grid, 512, attn_smem>>>(qb, kb, vb, ctx);
    hgemm_kernel<<<ggrid, 256>>>(ctx, ctx, 128, 128, W16 + OFF_O1, bo1, hp, hp, 1);

    // classifier
    final_kernel<<<M_ROWS / 256, 256>>>(hp, W_fin, b_fin, (float*)d_out);
}

// round 15
// speedup vs baseline: 1.0606x; 1.0447x over previous
#include <cuda_runtime.h>
#include <cuda_fp16.h>
#include <math.h>
#include <stdint.h>

#define M_ROWS 32768          // B*N
#define NB 32
#define NNODE 1024
#define NN2 (1024u * 1024u)

// weight offsets in g_W16 (half2 units); layout [k2][128] interleaved
#define OFF_RAW 0
#define OFF_D0  4096
#define OFF_D1  8192
#define OFF_Q0  16384
#define OFF_K0  32768
#define OFF_V0  49152
#define OFF_O0  65536
#define OFF_Q1  73728
#define OFF_K1  90112
#define OFF_V1  106496
#define OFF_O1  122880

// ---------------- scratch (device globals, allocation-free) ----------------
__device__ float   g_Q[2u * NN2];
__device__ __half2 g_W16[131072];
__device__ __half  g_P0[(size_t)NB * NN2];
__device__ __half  g_P1[(size_t)NB * NN2];
__device__ __half  g_X16[(size_t)M_ROWS * 64];
__device__ __half  g_hp [(size_t)M_ROWS * 128];
__device__ __half  g_h  [(size_t)M_ROWS * 128];
__device__ __half  g_h2 [(size_t)M_ROWS * 128];
__device__ __half  g_qb [(size_t)M_ROWS * 128];
__device__ __half  g_kb [(size_t)M_ROWS * 128];
__device__ __half  g_vb [(size_t)M_ROWS * 128];
__device__ __half  g_ctx[(size_t)M_ROWS * 128];

// ---------------- helpers ----------------
__device__ __forceinline__ uint32_t f2h2(float a, float b) {
    __half2 h = __floats2half2_rn(a, b);
    return *reinterpret_cast<uint32_t*>(&h);
}
__device__ __forceinline__ uint32_t h2bits(__half2 h) {
    return *reinterpret_cast<uint32_t*>(&h);
}
__device__ __forceinline__ float ex2f(float x) {
    float r;
    asm("ex2.approx.ftz.f32 %0, %1;" : "=f"(r) : "f"(x));
    return r;
}
__device__ __forceinline__ void cp16(uint32_t dst_smem, const void* src) {
    asm volatile("cp.async.ca.shared.global [%0], [%1], 16;\n"
                 :: "r"(dst_smem), "l"(src));
}
__device__ __forceinline__ void cp_commit() {
    asm volatile("cp.async.commit_group;\n");
}
__device__ __forceinline__ void cp_wait0() {
    asm volatile("cp.async.wait_group 0;\n");
}
__device__ __forceinline__ uint32_t smem_u32(const void* p) {
    return (uint32_t)__cvta_generic_to_shared(p);
}

__device__ __forceinline__ void mma_f16(float* d, const uint32_t* a,
                                        const uint32_t* b, const float* c) {
    asm volatile(
        "mma.sync.aligned.m16n8k16.row.col.f32.f16.f16.f32 "
        "{%0,%1,%2,%3}, {%4,%5,%6,%7}, {%8,%9}, {%10,%11,%12,%13};\n"
        : "=f"(d[0]), "=f"(d[1]), "=f"(d[2]), "=f"(d[3])
        : "r"(a[0]), "r"(a[1]), "r"(a[2]), "r"(a[3]),
          "r"(b[0]), "r"(b[1]),
          "f"(c[0]), "f"(c[1]), "f"(c[2]), "f"(c[3]));
}

// ---------------- Q[l] = sum_k softmax(theta)[l,k] * T[l,k] ----------------
__global__ void qmix_kernel(const float* __restrict__ T,
                            const float* __restrict__ th) {
    size_t i = (size_t)blockIdx.x * 256 + threadIdx.x;
    size_t l  = i >> 20;
    size_t ij = i & (NN2 - 1);
    float a = th[l*3+0], b = th[l*3+1], c = th[l*3+2];
    float m = fmaxf(a, fmaxf(b, c));
    float ea = __expf(a - m), eb = __expf(b - m), ec = __expf(c - m);
    float inv = 1.f / (ea + eb + ec);
    const float* Tl = T + l * 3u * NN2;
    g_Q[i] = inv * (ea * Tl[ij] + eb * Tl[NN2 + ij] + ec * Tl[2u*NN2 + ij]);
}

// ---------------- P16[l] = half(Q[l] ⊙ A), A read once ----------------
__global__ void pmul_kernel(const float* __restrict__ A) {
    size_t i  = ((size_t)blockIdx.x * 256 + threadIdx.x) * 4;
    size_t ij = i & (NN2 - 1);
    float4 a  = *reinterpret_cast<const float4*>(A + i);
    float4 q0 = *reinterpret_cast<const float4*>(g_Q + ij);
    float4 q1 = *reinterpret_cast<const float4*>(g_Q + NN2 + ij);
    uint2 u0, u1;
    u0.x = f2h2(q0.x*a.x, q0.y*a.y);
    u0.y = f2h2(q0.z*a.z, q0.w*a.w);
    u1.x = f2h2(q1.x*a.x, q1.y*a.y);
    u1.y = f2h2(q1.z*a.z, q1.w*a.w);
    *reinterpret_cast<uint2*>(g_P0 + i) = u0;
    *reinterpret_cast<uint2*>(g_P1 + i) = u1;
}

// ---------------- fp32 -> fp16 cast (for X) ----------------
__global__ void tohalf_kernel(const float* __restrict__ x, __half* __restrict__ o) {
    size_t i = ((size_t)blockIdx.x * 256 + threadIdx.x) * 4;
    float4 v = *reinterpret_cast<const float4*>(x + i);
    uint2 u;
    u.x = f2h2(v.x, v.y);
    u.y = f2h2(v.z, v.w);
    *reinterpret_cast<uint2*>(o + i) = u;
}

// ------- weight convert + interleave -------
__global__ void wconv_kernel(
    const float* r,  const float* d0, const float* d1,
    const float* q0, const float* k0, const float* v0, const float* o0,
    const float* q1, const float* k1, const float* v1, const float* o1)
{
    const float* srcs[11] = {r, d0, d1, q0, k0, v0, o0, q1, k1, v1, o1};
    const int    Ks[11]   = {64, 64, 128, 256, 256, 256, 128, 256, 256, 256, 128};
    const int    offs[11] = {OFF_RAW, OFF_D0, OFF_D1, OFF_Q0, OFF_K0, OFF_V0,
                             OFF_O0, OFF_Q1, OFF_K1, OFF_V1, OFF_O1};
    int m   = blockIdx.y;
    int idx = blockIdx.x * 256 + threadIdx.x;
    int K   = Ks[m];
    if (idx >= K * 64) return;
    const float* s = srcs[m];
    int k2 = idx >> 7, n = idx & 127;
    g_W16[offs[m] + idx] =
        __floats2half2_rn(s[(2*k2)*128 + n], s[(2*k2 + 1)*128 + n]);
}

// ---------- shared GEMM body (device function) ----------
struct GemmSmem {
    uint32_t As[2][128][20];   // 5120 words
    uint32_t Bs[2][16][136];   // 4352 words  -> total 9472 words
};

// mainloop only: leaves fp32 accumulators in acc[2][8][4]
__device__ __forceinline__ void hgemm_mainloop(
    GemmSmem* sm,
    const __half* A1, const __half* A2, int K1, int K,
    const __half2* W2, float acc[2][8][4], int row0)
{
    const int tid  = threadIdx.x;
    const int lane = tid & 31;
    const int w    = tid >> 5;
    const int wm   = w & 3;
    const int wn   = w >> 2;
    const int lr   = lane >> 2;
    const int lc   = lane & 3;
    const int sa_r   = tid >> 1;
    const int sa_k16 = (tid & 1) << 4;

#define CP_A(k0, bufi)                                                         \
    {                                                                          \
        int kg = (k0) + sa_k16;                                                \
        const __half* src = (kg < K1) ? A1 : A2;                               \
        int kk     = (kg < K1) ? kg : (kg - K1);                               \
        int stride = (kg < K1) ? K1 : (K - K1);                                \
        const __half* p = src + (size_t)(row0 + sa_r) * stride + kk;           \
        uint32_t d = smem_u32(&sm->As[bufi][sa_r][sa_k16 >> 1]);               \
        cp16(d, p);                                                            \
        cp16(d + 16, p + 8);                                                   \
    }

#define CP_B(k0, bufi)                                                         \
    {                                                                          \
        _Pragma("unroll")                                                      \
        for (int i = 0; i < 2; ++i) {                                          \
            int idx = tid + i * 256;                                           \
            int k2r = idx >> 5, nq = (idx & 31) << 2;                          \
            cp16(smem_u32(&sm->Bs[bufi][k2r][nq]),                             \
                 W2 + (size_t)(((k0) >> 1) + k2r) * 128 + nq);                 \
        }                                                                      \
    }

#pragma unroll
    for (int mt = 0; mt < 2; ++mt)
#pragma unroll
        for (int nt = 0; nt < 8; ++nt)
#pragma unroll
            for (int i = 0; i < 4; ++i) acc[mt][nt][i] = 0.f;

    CP_A(0, 0);
    CP_B(0, 0);
    cp_commit();

    int buf = 0;
    for (int k0 = 0; k0 < K; k0 += 32) {
        cp_wait0();
        __syncthreads();
        const bool has_next = (k0 + 32 < K);
        if (has_next) {
            CP_A(k0 + 32, buf ^ 1);
            CP_B(k0 + 32, buf ^ 1);
            cp_commit();
        }
#pragma unroll
        for (int s = 0; s < 2; ++s) {
            uint32_t a[2][4], b[8][2];
#pragma unroll
            for (int mt = 0; mt < 2; ++mt) {
                int rm = wm*32 + mt*16 + lr;
                a[mt][0] = sm->As[buf][rm    ][s*8 + lc    ];
                a[mt][1] = sm->As[buf][rm + 8][s*8 + lc    ];
                a[mt][2] = sm->As[buf][rm    ][s*8 + lc + 4];
                a[mt][3] = sm->As[buf][rm + 8][s*8 + lc + 4];
            }
#pragma unroll
            for (int nt = 0; nt < 8; ++nt) {
                int nb = wn*64 + nt*8 + lr;
                b[nt][0] = sm->Bs[buf][s*8 + lc    ][nb];
                b[nt][1] = sm->Bs[buf][s*8 + lc + 4][nb];
            }
#pragma unroll
            for (int mt = 0; mt < 2; ++mt)
#pragma unroll
                for (int nt = 0; nt < 8; ++nt)
                    mma_f16(acc[mt][nt], a[mt], b[nt], acc[mt][nt]);
        }
        buf ^= 1;
    }
#undef CP_A
#undef CP_B
}

__device__ __forceinline__ void hgemm_body(
    GemmSmem* sm,
    const __half* A1, const __half* A2, int K1, int K,
    const __half2* W2, const float* bias,
    const __half* base, __half* C, int relu, int row0)
{
    const int tid  = threadIdx.x;
    const int lane = tid & 31;
    const int w    = tid >> 5;
    const int wm   = w & 3;
    const int wn   = w >> 2;
    const int lr   = lane >> 2;
    const int lc   = lane & 3;

    float acc[2][8][4];
    hgemm_mainloop(sm, A1, A2, K1, K, W2, acc, row0);

#pragma unroll
    for (int mt = 0; mt < 2; ++mt) {
#pragma unroll
        for (int nt = 0; nt < 8; ++nt) {
            int col = wn*64 + nt*8 + 2*lc;
            float b0 = bias[col], b1 = bias[col+1];
#pragma unroll
            for (int half = 0; half < 2; ++half) {
                int row = row0 + wm*32 + mt*16 + lr + half*8;
                float v0 = acc[mt][nt][half*2+0] + b0;
                float v1 = acc[mt][nt][half*2+1] + b1;
                if (relu) { v0 = fmaxf(v0, 0.f); v1 = fmaxf(v1, 0.f); }
                if (base) {
                    __half2 bh = *reinterpret_cast<const __half2*>(
                        base + (size_t)row * 128 + col);
                    float2 bf = __half22float2(bh);
                    v0 += bf.x; v1 += bf.y;
                }
                *reinterpret_cast<uint32_t*>(C + (size_t)row * 128 + col) =
                    f2h2(v0, v1);
            }
        }
    }
}

__global__ __launch_bounds__(256) void hgemm_kernel(
    const __half* __restrict__ A1, const __half* __restrict__ A2, int K1, int K,
    const __half2* __restrict__ W2, const float* __restrict__ bias,
    const __half* __restrict__ base, __half* __restrict__ C, int relu)
{
    __shared__ GemmSmem sm;
    hgemm_body(&sm, A1, A2, K1, K, W2, bias, base, C, relu, blockIdx.x << 7);
}

// batched q/k/v: blockIdx.y selects the matrix
__global__ __launch_bounds__(256) void qkv3_kernel(
    const __half* __restrict__ A1, const __half* __restrict__ A2,
    const __half2* __restrict__ Wq, const __half2* __restrict__ Wk,
    const __half2* __restrict__ Wv,
    const float* __restrict__ bq, const float* __restrict__ bk,
    const float* __restrict__ bv,
    __half* __restrict__ Oq, __half* __restrict__ Ok, __half* __restrict__ Ov)
{
    __shared__ GemmSmem sm;
    const int m = blockIdx.y;
    const __half2* W2 = (m == 0) ? Wq : (m == 1) ? Wk : Wv;
    const float* bias = (m == 0) ? bq : (m == 1) ? bk : bv;
    __half* C         = (m == 0) ? Oq : (m == 1) ? Ok : Ov;
    hgemm_body(&sm, A1, A2, 128, 256, W2, bias, nullptr, C, 0, blockIdx.x << 7);
}

// ==== final O-projection fused with classifier ====
// hp_new = relu(ctx@Wo + bo) + hp_old (fp16-rounded in smem),
// out = hp_new @ W_fin + b_fin   (identical math/order to old final_kernel)
__global__ __launch_bounds__(256) void ofinal_kernel(
    const __half* __restrict__ A1, const __half2* __restrict__ W2,
    const float* __restrict__ bias, const __half* __restrict__ base,
    const float* __restrict__ Wfin, const float* __restrict__ bfin,
    float* __restrict__ out)
{
    __shared__ GemmSmem sm;
    __shared__ float Wf[256];
    __shared__ float bf2[2];

    const int tid  = threadIdx.x;
    const int lane = tid & 31;
    const int w    = tid >> 5;
    const int wm   = w & 3;
    const int wn   = w >> 2;
    const int lr   = lane >> 2;
    const int lc   = lane & 3;
    const int row0 = blockIdx.x << 7;

    if (tid < 256) Wf[tid] = Wfin[tid];
    if (tid < 2)   bf2[tid] = bfin[tid];

    float acc[2][8][4];
    hgemm_mainloop(&sm, A1, A1, 128, 128, W2, acc, row0);

    __syncthreads();   // all As/Bs reads complete before overlay

    // overlay hp tile [128 rows][64 half2 + pad] on GemmSmem (needs 8448 <= 9472 words)
    uint32_t* ZS = reinterpret_cast<uint32_t*>(&sm);
#define ZSX(r, c2) ZS[(r)*66 + (c2)]

#pragma unroll
    for (int mt = 0; mt < 2; ++mt) {
#pragma unroll
        for (int nt = 0; nt < 8; ++nt) {
            int col = wn*64 + nt*8 + 2*lc;
            float b0 = bias[col], b1 = bias[col+1];
#pragma unroll
            for (int half = 0; half < 2; ++half) {
                int row = wm*32 + mt*16 + lr + half*8;
                float v0 = fmaxf(acc[mt][nt][half*2+0] + b0, 0.f);
                float v1 = fmaxf(acc[mt][nt][half*2+1] + b1, 0.f);
                __half2 bh = *reinterpret_cast<const __half2*>(
                    base + (size_t)(row0 + row) * 128 + col);
                float2 bv = __half22float2(bh);
                v0 += bv.x; v1 += bv.y;
                ZSX(row, col >> 1) = f2h2(v0, v1);
            }
        }
    }
    __syncthreads();

    // classifier: thread t -> (row = t>>1, cls = t&1); identical order to final_kernel
    {
        int row = tid >> 1;
        int cls = tid & 1;
        float a = bf2[cls];
#pragma unroll
        for (int k2 = 0; k2 < 64; ++k2) {
            __half2 hv = *reinterpret_cast<__half2*>(&ZSX(row, k2));
            float2 f = __half22float2(hv);
            a += f.x * Wf[4*k2 + cls] + f.y * Wf[4*k2 + 2 + cls];
        }
        out[(size_t)(row0 + row) * 2 + cls] = a;
    }
#undef ZSX
}

// ====== fused diffusion + linear: Hout = relu((P16 @ Hin) @ Wd + bias) ======
template<int BN>
__global__ __launch_bounds__(256) void diff_fused_kernel(
    const __half* __restrict__ P, const __half* __restrict__ Hin,
    const __half2* __restrict__ Wd2, const float* __restrict__ bias,
    __half* __restrict__ Hout)
{
    constexpr int WN = BN / 2;
    constexpr int NT = WN / 8;
    constexpr int ZW = BN / 2 + 4;

    extern __shared__ uint32_t dsm[];
    uint32_t* AS = dsm;                    // [2][128][20]
    uint32_t* BS = dsm + 5120;             // [2][16][136]
    uint32_t* ZS = dsm + 5120 + 4352;      // [128][ZW]
#define ASX(bufi, r, c) AS[(bufi)*2560 + (r)*20 + (c)]
#define BSX(bufi, r, c) BS[(bufi)*2176 + (r)*136 + (c)]
#define ZSX(r, c)       ZS[(r)*ZW + (c)]

    const int tid  = threadIdx.x;
    const int lane = tid & 31;
    const int w    = tid >> 5;
    const int wm   = w & 3;
    const int wn   = w >> 2;
    const int lr   = lane >> 2;
    const int lc   = lane & 3;
    const int b    = blockIdx.z;
    const int i0   = blockIdx.x << 7;
    const size_t pb = (size_t)b * NN2;
    const size_t hb = (size_t)b * NNODE * BN;

    const int sa_r   = tid >> 1;
    const int sa_k16 = (tid & 1) << 4;

    uint4 bu0, bu1;

#define CP_P(j0, bufi)                                                         \
    {                                                                          \
        const __half* p = P + pb + (size_t)(i0 + sa_r) * NNODE + (j0) + sa_k16;\
        uint32_t d = smem_u32(&ASX(bufi, sa_r, sa_k16 >> 1));                  \
        cp16(d, p);                                                            \
        cp16(d + 16, p + 8);                                                   \
    }

#define DIFF_LDG_B(j0)                                                         \
    {                                                                          \
        if (BN == 128) {                                                       \
            int k2r = tid >> 4, nh = (tid & 15) * 8;                           \
            const __half* q = Hin + hb + (size_t)((j0) + 2*k2r) * BN + nh;     \
            bu0 = *reinterpret_cast<const uint4*>(q);                          \
            bu1 = *reinterpret_cast<const uint4*>(q + BN);                     \
        } else {                                                               \
            int k2r = tid >> 4, nh = (tid & 15) * 4;                           \
            const __half* q = Hin + hb + (size_t)((j0) + 2*k2r) * BN + nh;     \
            uint2 t0 = *reinterpret_cast<const uint2*>(q);                     \
            uint2 t1 = *reinterpret_cast<const uint2*>(q + BN);                \
            bu0.x = t0.x; bu0.y = t0.y; bu1.x = t1.x; bu1.y = t1.y;            \
        }                                                                      \
    }

#define DIFF_STS_B(bufi)                                                       \
    {                                                                          \
        if (BN == 128) {                                                       \
            int k2r = tid >> 4, nh = (tid & 15) * 8;                           \
            uint4 v0, v1;                                                      \
            v0.x = __byte_perm(bu0.x, bu1.x, 0x5410);                          \
            v0.y = __byte_perm(bu0.x, bu1.x, 0x7632);                          \
            v0.z = __byte_perm(bu0.y, bu1.y, 0x5410);                          \
            v0.w = __byte_perm(bu0.y, bu1.y, 0x7632);                          \
            v1.x = __byte_perm(bu0.z, bu1.z, 0x5410);                          \
            v1.y = __byte_perm(bu0.z, bu1.z, 0x7632);                          \
            v1.z = __byte_perm(bu0.w, bu1.w, 0x5410);                          \
            v1.w = __byte_perm(bu0.w, bu1.w, 0x7632);                          \
            *reinterpret_cast<uint4*>(&BSX(bufi, k2r, nh    )) = v0;           \
            *reinterpret_cast<uint4*>(&BSX(bufi, k2r, nh + 4)) = v1;           \
        } else {                                                               \
            int k2r = tid >> 4, nh = (tid & 15) * 4;                           \
            uint4 v0;                                                          \
            v0.x = __byte_perm(bu0.x, bu1.x, 0x5410);                          \
            v0.y = __byte_perm(bu0.x, bu1.x, 0x7632);                          \
            v0.z = __byte_perm(bu0.y, bu1.y, 0x5410);                          \
            v0.w = __byte_perm(bu0.y, bu1.y, 0x7632);                          \
            *reinterpret_cast<uint4*>(&BSX(bufi, k2r, nh)) = v0;               \
        }                                                                      \
    }

    // ---------------- phase 1: z = P @ Hin ----------------
    float acc[2][NT][4];
#pragma unroll
    for (int mt = 0; mt < 2; ++mt)
#pragma unroll
        for (int nt = 0; nt < NT; ++nt)
#pragma unroll
            for (int i = 0; i < 4; ++i) acc[mt][nt][i] = 0.f;

    DIFF_LDG_B(0);
    CP_P(0, 0);
    cp_commit();
    DIFF_STS_B(0);

    int buf = 0;
    for (int j0 = 0; j0 < NNODE; j0 += 32) {
        cp_wait0();
        __syncthreads();
        const bool has_next = (j0 + 32 < NNODE);
        if (has_next) {
            CP_P(j0 + 32, buf ^ 1);
            cp_commit();
            DIFF_LDG_B(j0 + 32);
        }
#pragma unroll
        for (int s = 0; s < 2; ++s) {
            uint32_t a[2][4], bf[NT][2];
#pragma unroll
            for (int mt = 0; mt < 2; ++mt) {
                int rm = wm*32 + mt*16 + lr;
                a[mt][0] = ASX(buf, rm    , s*8 + lc    );
                a[mt][1] = ASX(buf, rm + 8, s*8 + lc    );
                a[mt][2] = ASX(buf, rm    , s*8 + lc + 4);
                a[mt][3] = ASX(buf, rm + 8, s*8 + lc + 4);
            }
#pragma unroll
            for (int nt = 0; nt < NT; ++nt) {
                int nb = wn*WN + nt*8 + lr;
                bf[nt][0] = BSX(buf, s*8 + lc    , nb);
                bf[nt][1] = BSX(buf, s*8 + lc + 4, nb);
            }
#pragma unroll
            for (int mt = 0; mt < 2; ++mt)
#pragma unroll
                for (int nt = 0; nt < NT; ++nt)
                    mma_f16(acc[mt][nt], a[mt], bf[nt], acc[mt][nt]);
        }
        if (has_next) DIFF_STS_B(buf ^ 1);
        buf ^= 1;
    }

#pragma unroll
    for (int mt = 0; mt < 2; ++mt) {
#pragma unroll
        for (int nt = 0; nt < NT; ++nt) {
            int col = wn*WN + nt*8 + 2*lc;
#pragma unroll
            for (int half = 0; half < 2; ++half) {
                int row = wm*32 + mt*16 + lr + half*8;
                ZSX(row, col >> 1) =
                    f2h2(acc[mt][nt][half*2+0], acc[mt][nt][half*2+1]);
            }
        }
    }
    __syncthreads();

    // ---------------- phase 2: Hout = relu(z @ Wd + bias) ----------------
#define CP_W(k0, bufi)                                                         \
    {                                                                          \
        _Pragma("unroll")                                                      \
        for (int i = 0; i < 2; ++i) {                                          \
            int idx = tid + i * 256;                                           \
            int k2r = idx >> 5, nq = (idx & 31) << 2;                          \
            cp16(smem_u32(&BSX(bufi, k2r, nq)),                                \
                 Wd2 + (size_t)(((k0) >> 1) + k2r) * 128 + nq);                \
        }                                                                      \
    }

    float acc2[2][8][4];
#pragma unroll
    for (int mt = 0; mt < 2; ++mt)
#pragma unroll
        for (int nt = 0; nt < 8; ++nt)
#pragma unroll
            for (int i = 0; i < 4; ++i) acc2[mt][nt][i] = 0.f;

    CP_W(0, 0);
    cp_commit();

    buf = 0;
    for (int k0 = 0; k0 < BN; k0 += 32) {
        cp_wait0();
        __syncthreads();
        const bool has_next = (k0 + 32 < BN);
        if (has_next) {
            CP_W(k0 + 32, buf ^ 1);
            cp_commit();
        }
        const int k2b = k0 >> 1;
#pragma unroll
        for (int s = 0; s < 2; ++s) {
            uint32_t a[2][4], bfr[8][2];
#pragma unroll
            for (int mt = 0; mt < 2; ++mt) {
                int rm = wm*32 + mt*16 + lr;
                a[mt][0] = ZSX(rm    , k2b + s*8 + lc    );
                a[mt][1] = ZSX(rm + 8, k2b + s*8 + lc    );
                a[mt][2] = ZSX(rm    , k2b + s*8 + lc + 4);
                a[mt][3] = ZSX(rm + 8, k2b + s*8 + lc + 4);
            }
#pragma unroll
            for (int nt = 0; nt < 8; ++nt) {
                int nb = wn*64 + nt*8 + lr;
                bfr[nt][0] = BSX(buf, s*8 + lc    , nb);
                bfr[nt][1] = BSX(buf, s*8 + lc + 4, nb);
            }
#pragma unroll
            for (int mt = 0; mt < 2; ++mt)
#pragma unroll
                for (int nt = 0; nt < 8; ++nt)
                    mma_f16(acc2[mt][nt], a[mt], bfr[nt], acc2[mt][nt]);
        }
        buf ^= 1;
    }

#pragma unroll
    for (int mt = 0; mt < 2; ++mt) {
#pragma unroll
        for (int nt = 0; nt < 8; ++nt) {
            int col = wn*64 + nt*8 + 2*lc;
            float b0 = bias[col], b1 = bias[col+1];
#pragma unroll
            for (int half = 0; half < 2; ++half) {
                int row = i0 + wm*32 + mt*16 + lr + half*8;
                float v0 = fmaxf(acc2[mt][nt][half*2+0] + b0, 0.f);
                float v1 = fmaxf(acc2[mt][nt][half*2+1] + b1, 0.f);
                *reinterpret_cast<uint32_t*>(
                    Hout + ((size_t)b * NNODE + row) * 128 + col) = f2h2(v0, v1);
            }
        }
    }
#undef CP_P
#undef DIFF_LDG_B
#undef DIFF_STS_B
#undef CP_W
#undef ASX
#undef BSX
#undef ZSX
}

// ========== fp16 flash attention: 256 q / 512 thr; P register-resident ==========
__global__ __launch_bounds__(512) void attn_mma_kernel(
    const __half* __restrict__ Qg, const __half* __restrict__ Kg,
    const __half* __restrict__ Vg, __half* __restrict__ Og)
{
    extern __shared__ uint32_t asmem[];
    uint32_t (*Ps2)[36] = reinterpret_cast<uint32_t(*)[36]>(asmem);            // 256 rows (Q staging only)
    uint32_t (*Ks2)[36] = reinterpret_cast<uint32_t(*)[36]>(asmem + 256*36);   // 2*64 rows
    uint32_t (*Vs2)[72] = reinterpret_cast<uint32_t(*)[72]>(asmem + 384*36);   // 2*32 rows

    const int tid  = threadIdx.x;
    const int lane = tid & 31;
    const int w    = tid >> 5;
    const int lr   = lane >> 2;
    const int lc   = lane & 3;
    const int b    = blockIdx.z, h = blockIdx.y;
    const int q0   = blockIdx.x << 8;
    const size_t rb = (size_t)b * NNODE;
    const int hoff = h * 64;
    const float SC = 0.125f * 1.4426950408889634f;
    const __half2 h2sc = __float2half2_rn(SC);

    {
        int r   = w*16 + (lane >> 1);
        int seg = (lane & 1) * 32;
        const __half* p = Qg + (rb + q0 + r) * 128 + hoff + seg;
#pragma unroll
        for (int jj = 0; jj < 4; ++jj) {
            uint4 u = *reinterpret_cast<const uint4*>(p + 8*jj);
            *reinterpret_cast<uint4*>(&Ps2[r][(seg>>1) + 4*jj]) = u;
        }
    }
    __syncwarp();

    uint32_t qa[4][4];
#pragma unroll
    for (int ks = 0; ks < 4; ++ks) {
        qa[ks][0] = Ps2[w*16 + lr    ][ks*8 + lc    ];
        qa[ks][1] = Ps2[w*16 + lr + 8][ks*8 + lc    ];
        qa[ks][2] = Ps2[w*16 + lr    ][ks*8 + lc + 4];
        qa[ks][3] = Ps2[w*16 + lr + 8][ks*8 + lc + 4];
#pragma unroll
        for (int i = 0; i < 4; ++i) {
            __half2 hv = *reinterpret_cast<__half2*>(&qa[ks][i]);
            hv = __hmul2(hv, h2sc);
            qa[ks][i] = h2bits(hv);
        }
    }

    float m0 = -1e30f, m1 = -1e30f, l0 = 0.f, l1 = 0.f;
    float oacc[8][4];
#pragma unroll
    for (int nt = 0; nt < 8; ++nt)
#pragma unroll
        for (int i = 0; i < 4; ++i) oacc[nt][i] = 0.f;

    uint2 uv0, uv1;
    const int kr   = tid >> 3;
    const int kseg = (tid & 7) << 3;
    const int vk2r = tid >> 4;
    const int vdq  = (tid & 15) * 4;

#define CP_K(j0, bufi)                                                         \
    {                                                                          \
        const __half* p = Kg + (rb + (j0) + kr) * 128 + hoff + kseg;           \
        cp16(smem_u32(&Ks2[(bufi)*64 + kr][kseg >> 1]), p);                    \
    }

#define LDG_V(j0)                                                              \
    {                                                                          \
        const __half* q = Vg + (rb + (j0) + 2*vk2r) * 128 + hoff + vdq;        \
        uv0 = *reinterpret_cast<const uint2*>(q);                              \
        uv1 = *reinterpret_cast<const uint2*>(q + 128);                        \
    }

#define STS_V(bufi)                                                            \
    {                                                                          \
        uint4 v0;                                                              \
        v0.x = __byte_perm(uv0.x, uv1.x, 0x5410);                              \
        v0.y = __byte_perm(uv0.x, uv1.x, 0x7632);                              \
        v0.z = __byte_perm(uv0.y, uv1.y, 0x5410);                              \
        v0.w = __byte_perm(uv0.y, uv1.y, 0x7632);                              \
        *reinterpret_cast<uint4*>(&Vs2[(bufi)*32 + vk2r][vdq]) = v0;           \
    }

    CP_K(0, 0);
    cp_commit();
    LDG_V(0);
    STS_V(0);

    for (int c = 0; c < NNODE/64; ++c) {
        const int buf = c & 1;
        cp_wait0();
        __syncthreads();

        const bool has_next = (c + 1 < NNODE/64);
        if (has_next) {
            CP_K((c + 1) * 64, buf ^ 1);
            cp_commit();
            LDG_V((c + 1) * 64);
        }

        float sacc[8][4];
#pragma unroll
        for (int nt = 0; nt < 8; ++nt)
#pragma unroll
            for (int i = 0; i < 4; ++i) sacc[nt][i] = 0.f;
#pragma unroll
        for (int ks = 0; ks < 4; ++ks) {
#pragma unroll
            for (int nt = 0; nt < 8; ++nt) {
                uint32_t bf[2];
                bf[0] = Ks2[buf*64 + nt*8 + lr][ks*8 + lc    ];
                bf[1] = Ks2[buf*64 + nt*8 + lr][ks*8 + lc + 4];
                mma_f16(sacc[nt], qa[ks], bf, sacc[nt]);
            }
        }

        float rmax0 = -1e30f, rmax1 = -1e30f;
#pragma unroll
        for (int nt = 0; nt < 8; ++nt) {
            rmax0 = fmaxf(rmax0, fmaxf(sacc[nt][0], sacc[nt][1]));
            rmax1 = fmaxf(rmax1, fmaxf(sacc[nt][2], sacc[nt][3]));
        }
        rmax0 = fmaxf(rmax0, __shfl_xor_sync(0xffffffffu, rmax0, 1));
        rmax0 = fmaxf(rmax0, __shfl_xor_sync(0xffffffffu, rmax0, 2));
        rmax1 = fmaxf(rmax1, __shfl_xor_sync(0xffffffffu, rmax1, 1));
        rmax1 = fmaxf(rmax1, __shfl_xor_sync(0xffffffffu, rmax1, 2));

        float mn0 = fmaxf(m0, rmax0), mn1 = fmaxf(m1, rmax1);
        float cr0 = ex2f(m0 - mn0), cr1 = ex2f(m1 - mn1);
        m0 = mn0; m1 = mn1;

        uint32_t ph0[8], ph1[8];
        float rs0 = 0.f, rs1 = 0.f;
#pragma unroll
        for (int nt = 0; nt < 8; ++nt) {
            float p00 = ex2f(sacc[nt][0] - mn0);
            float p01 = ex2f(sacc[nt][1] - mn0);
            float p10 = ex2f(sacc[nt][2] - mn1);
            float p11 = ex2f(sacc[nt][3] - mn1);
            __half2 h0 = __floats2half2_rn(p00, p01);
            __half2 h1 = __floats2half2_rn(p10, p11);
            float2 f0 = __half22float2(h0);
            float2 f1 = __half22float2(h1);
            rs0 += f0.x + f0.y;
            rs1 += f1.x + f1.y;
            ph0[nt] = h2bits(h0);
            ph1[nt] = h2bits(h1);
        }
        rs0 += __shfl_xor_sync(0xffffffffu, rs0, 1);
        rs0 += __shfl_xor_sync(0xffffffffu, rs0, 2);
        rs1 += __shfl_xor_sync(0xffffffffu, rs1, 1);
        rs1 += __shfl_xor_sync(0xffffffffu, rs1, 2);
        l0 = l0 * cr0 + rs0;
        l1 = l1 * cr1 + rs1;

#pragma unroll
        for (int nt = 0; nt < 8; ++nt) {
            oacc[nt][0] *= cr0; oacc[nt][1] *= cr0;
            oacc[nt][2] *= cr1; oacc[nt][3] *= cr1;
        }

        if (has_next) STS_V(buf ^ 1);

#pragma unroll
        for (int ks = 0; ks < 4; ++ks) {
            uint32_t pa[4];
            pa[0] = ph0[2*ks    ];
            pa[1] = ph1[2*ks    ];
            pa[2] = ph0[2*ks + 1];
            pa[3] = ph1[2*ks + 1];
#pragma unroll
            for (int nt = 0; nt < 8; ++nt) {
                uint32_t bf[2];
                bf[0] = Vs2[buf*32 + ks*8 + lc    ][nt*8 + lr];
                bf[1] = Vs2[buf*32 + ks*8 + lc + 4][nt*8 + lr];
                mma_f16(oacc[nt], pa, bf, oacc[nt]);
            }
        }
    }

    float inv0 = 1.f / l0, inv1 = 1.f / l1;
#pragma unroll
    for (int nt = 0; nt < 8; ++nt) {
        int col = hoff + nt*8 + 2*lc;
        *reinterpret_cast<uint32_t*>(Og + (rb + q0 + w*16 + lr    ) * 128 + col) =
            f2h2(oacc[nt][0] * inv0, oacc[nt][1] * inv0);
        *reinterpret_cast<uint32_t*>(Og + (rb + q0 + w*16 + lr + 8) * 128 + col) =
            f2h2(oacc[nt][2] * inv1, oacc[nt][3] * inv1);
    }
#undef CP_K
#undef LDG_V
#undef STS_V
}

// ---------------- launch ----------------
extern "C" void kernel_launch(void* const* d_in, const int* in_sizes, int n_in,
                              void* d_out, int out_size) {
    const float* X     = (const float*)d_in[0];
    const float* A     = (const float*)d_in[1];
    const float* T     = (const float*)d_in[2];
    const float* theta = (const float*)d_in[3];
    const float* W_raw = (const float*)d_in[4];
    const float* b_raw = (const float*)d_in[5];
    const float* Wd0   = (const float*)d_in[6];
    const float* bd0   = (const float*)d_in[7];
    const float* Wd1   = (const float*)d_in[8];
    const float* bd1   = (const float*)d_in[9];
    const float* W_fin = (const float*)d_in[10];
    const float* b_fin = (const float*)d_in[11];
    const float* Wq0 = (const float*)d_in[12]; const float* bq0 = (const float*)d_in[13];
    const float* Wk0 = (const float*)d_in[14]; const float* bk0 = (const float*)d_in[15];
    const float* Wv0 = (const float*)d_in[16]; const float* bv0 = (const float*)d_in[17];
    const float* Wo0 = (const float*)d_in[18]; const float* bo0 = (const float*)d_in[19];
    const float* Wq1 = (const float*)d_in[20]; const float* bq1 = (const float*)d_in[21];
    const float* Wk1 = (const float*)d_in[22]; const float* bk1 = (const float*)d_in[23];
    const float* Wv1 = (const float*)d_in[24]; const float* bv1 = (const float*)d_in[25];
    const float* Wo1 = (const float*)d_in[26]; const float* bo1 = (const float*)d_in[27];

    __half *P0, *P1, *X16, *hp, *h, *h2, *qb, *kb, *vb, *ctx;
    __half2* W16;
    cudaGetSymbolAddress((void**)&P0,  g_P0);
    cudaGetSymbolAddress((void**)&P1,  g_P1);
    cudaGetSymbolAddress((void**)&X16, g_X16);
    cudaGetSymbolAddress((void**)&hp,  g_hp);
    cudaGetSymbolAddress((void**)&h,   g_h);
    cudaGetSymbolAddress((void**)&h2,  g_h2);
    cudaGetSymbolAddress((void**)&qb,  g_qb);
    cudaGetSymbolAddress((void**)&kb,  g_kb);
    cudaGetSymbolAddress((void**)&vb,  g_vb);
    cudaGetSymbolAddress((void**)&ctx, g_ctx);
    cudaGetSymbolAddress((void**)&W16, g_W16);

    const int attn_smem  = (256*36 + 128*36 + 64*72) * (int)sizeof(uint32_t); // 73728
    const int diff64_sm  = (5120 + 4352 + 128*36) * (int)sizeof(uint32_t);    // 56320
    const int diff128_sm = (5120 + 4352 + 128*68) * (int)sizeof(uint32_t);    // 72704
    cudaFuncSetAttribute(attn_mma_kernel,
        cudaFuncAttributeMaxDynamicSharedMemorySize, attn_smem);
    cudaFuncSetAttribute(diff_fused_kernel<64>,
        cudaFuncAttributeMaxDynamicSharedMemorySize, diff64_sm);
    cudaFuncSetAttribute(diff_fused_kernel<128>,
        cudaFuncAttributeMaxDynamicSharedMemorySize, diff128_sm);

    const int ggrid = M_ROWS / 128;
    dim3 dgrid(NNODE / 128, 1, NB);
    dim3 qkv_grid(ggrid, 3);
    dim3 attn_grid(NNODE / 256, 2, NB);

    qmix_kernel<<<2 * 1024 * 1024 / 256, 256>>>(T, theta);
    pmul_kernel<<<NB * 1024 * 1024 / 1024, 256>>>(A);
    tohalf_kernel<<<M_ROWS * 64 / 1024, 256>>>(X, X16);
    wconv_kernel<<<dim3(64, 11), 256>>>(W_raw, Wd0, Wd1,
                                        Wq0, Wk0, Wv0, Wo0,
                                        Wq1, Wk1, Wv1, Wo1);

    // raw projection: hp = X @ W_raw + b_raw
    hgemm_kernel<<<ggrid, 256>>>(X16, X16, 64, 64, W16 + OFF_RAW, b_raw, nullptr, hp, 0);

    // layer 0: fused diffusion+linear, then attention block
    diff_fused_kernel<64><<<dgrid, 256, diff64_sm>>>(P0, X16, W16 + OFF_D0, bd0, h);
    qkv3_kernel<<<qkv_grid, 256>>>(h, hp, W16 + OFF_Q0, W16 + OFF_K0, W16 + OFF_V0,
                                   bq0, bk0, bv0, qb, kb, vb);
    attn_mma_kernel<<<attn_grid, 512, attn_smem>>>(qb, kb, vb, ctx);
    hgemm_kernel<<<ggrid, 256>>>(ctx, ctx, 128, 128, W16 + OFF_O0, bo0, nullptr, hp, 1);

    // layer 1 (no aliasing: diff writes h2)
    diff_fused_kernel<128><<<dgrid, 256, diff128_sm>>>(P1, h, W16 + OFF_D1, bd1, h2);
    qkv3_kernel<<<qkv_grid, 256>>>(h2, hp, W16 + OFF_Q1, W16 + OFF_K1, W16 + OFF_V1,
                                   bq1, bk1, bv1, qb, kb, vb);
    attn_mma_kernel<<<attn_grid, 512, attn_smem>>>(qb, kb, vb, ctx);

    // final O-projection fused with residual add + classifier
    ofinal_kernel<<<ggrid, 256>>>(ctx, W16 + OFF_O1, bo1, hp,
                                  W_fin, b_fin, (float*)d_out);
}

// round 17
// speedup vs baseline: 1.0729x; 1.0116x over previous
#include <cuda_runtime.h>
#include <cuda_fp16.h>
#include <math.h>
#include <stdint.h>

#define M_ROWS 32768          // B*N
#define NB 32
#define NNODE 1024
#define NN2 (1024u * 1024u)

// weight offsets in g_W16 (half2 units); layout [k2][128] interleaved
#define OFF_RAW 0
#define OFF_D0  4096
#define OFF_D1  8192
#define OFF_Q0  16384
#define OFF_K0  32768
#define OFF_V0  49152
#define OFF_O0  65536
#define OFF_Q1  73728
#define OFF_K1  90112
#define OFF_V1  106496
#define OFF_O1  122880

// ---------------- scratch (device globals, allocation-free) ----------------
__device__ float   g_Q[2u * NN2];
__device__ __half2 g_W16[131072];
__device__ __half  g_P0[(size_t)NB * NN2];
__device__ __half  g_P1[(size_t)NB * NN2];
__device__ __half  g_X16[(size_t)M_ROWS * 64];
__device__ __half  g_hp [(size_t)M_ROWS * 128];
__device__ __half  g_h  [(size_t)M_ROWS * 128];
__device__ __half  g_h2 [(size_t)M_ROWS * 128];
__device__ __half  g_qb [(size_t)M_ROWS * 128];
__device__ __half  g_kb [(size_t)M_ROWS * 128];
__device__ __half  g_vb [(size_t)M_ROWS * 128];
__device__ __half  g_ctx[(size_t)M_ROWS * 128];

// ---------------- helpers ----------------
__device__ __forceinline__ uint32_t f2h2(float a, float b) {
    __half2 h = __floats2half2_rn(a, b);
    return *reinterpret_cast<uint32_t*>(&h);
}
__device__ __forceinline__ uint32_t h2bits(__half2 h) {
    return *reinterpret_cast<uint32_t*>(&h);
}
__device__ __forceinline__ float ex2f(float x) {
    float r;
    asm("ex2.approx.ftz.f32 %0, %1;" : "=f"(r) : "f"(x));
    return r;
}
__device__ __forceinline__ void cp16(uint32_t dst_smem, const void* src) {
    asm volatile("cp.async.ca.shared.global [%0], [%1], 16;\n"
                 :: "r"(dst_smem), "l"(src));
}
__device__ __forceinline__ void cp_commit() {
    asm volatile("cp.async.commit_group;\n");
}
__device__ __forceinline__ void cp_wait0() {
    asm volatile("cp.async.wait_group 0;\n");
}
__device__ __forceinline__ void cp_wait1() {
    asm volatile("cp.async.wait_group 1;\n");
}
__device__ __forceinline__ uint32_t smem_u32(const void* p) {
    return (uint32_t)__cvta_generic_to_shared(p);
}

__device__ __forceinline__ void mma_f16(float* d, const uint32_t* a,
                                        const uint32_t* b, const float* c) {
    asm volatile(
        "mma.sync.aligned.m16n8k16.row.col.f32.f16.f16.f32 "
        "{%0,%1,%2,%3}, {%4,%5,%6,%7}, {%8,%9}, {%10,%11,%12,%13};\n"
        : "=f"(d[0]), "=f"(d[1]), "=f"(d[2]), "=f"(d[3])
        : "r"(a[0]), "r"(a[1]), "r"(a[2]), "r"(a[3]),
          "r"(b[0]), "r"(b[1]),
          "f"(c[0]), "f"(c[1]), "f"(c[2]), "f"(c[3]));
}

// ---------------- Q[l] = sum_k softmax(theta)[l,k] * T[l,k] ----------------
__global__ void qmix_kernel(const float* __restrict__ T,
                            const float* __restrict__ th) {
    size_t i = (size_t)blockIdx.x * 256 + threadIdx.x;
    size_t l  = i >> 20;
    size_t ij = i & (NN2 - 1);
    float a = th[l*3+0], b = th[l*3+1], c = th[l*3+2];
    float m = fmaxf(a, fmaxf(b, c));
    float ea = __expf(a - m), eb = __expf(b - m), ec = __expf(c - m);
    float inv = 1.f / (ea + eb + ec);
    const float* Tl = T + l * 3u * NN2;
    g_Q[i] = inv * (ea * Tl[ij] + eb * Tl[NN2 + ij] + ec * Tl[2u*NN2 + ij]);
}

// ---------------- P16[l] = half(Q[l] ⊙ A), A read once ----------------
__global__ void pmul_kernel(const float* __restrict__ A) {
    size_t i  = ((size_t)blockIdx.x * 256 + threadIdx.x) * 4;
    size_t ij = i & (NN2 - 1);
    float4 a  = *reinterpret_cast<const float4*>(A + i);
    float4 q0 = *reinterpret_cast<const float4*>(g_Q + ij);
    float4 q1 = *reinterpret_cast<const float4*>(g_Q + NN2 + ij);
    uint2 u0, u1;
    u0.x = f2h2(q0.x*a.x, q0.y*a.y);
    u0.y = f2h2(q0.z*a.z, q0.w*a.w);
    u1.x = f2h2(q1.x*a.x, q1.y*a.y);
    u1.y = f2h2(q1.z*a.z, q1.w*a.w);
    *reinterpret_cast<uint2*>(g_P0 + i) = u0;
    *reinterpret_cast<uint2*>(g_P1 + i) = u1;
}

// ---------------- fp32 -> fp16 cast (for X) ----------------
__global__ void tohalf_kernel(const float* __restrict__ x, __half* __restrict__ o) {
    size_t i = ((size_t)blockIdx.x * 256 + threadIdx.x) * 4;
    float4 v = *reinterpret_cast<const float4*>(x + i);
    uint2 u;
    u.x = f2h2(v.x, v.y);
    u.y = f2h2(v.z, v.w);
    *reinterpret_cast<uint2*>(o + i) = u;
}

// ------- weight convert + interleave (switch-select + 4-wide) -------
__global__ void wconv_kernel(
    const float* r,  const float* d0, const float* d1,
    const float* q0, const float* k0, const float* v0, const float* o0,
    const float* q1, const float* k1, const float* v1, const float* o1)
{
    int m = blockIdx.y;
    const float* s;
    int K, off;
    switch (m) {
        case 0:  s = r;  K = 64;  off = OFF_RAW; break;
        case 1:  s = d0; K = 64;  off = OFF_D0;  break;
        case 2:  s = d1; K = 128; off = OFF_D1;  break;
        case 3:  s = q0; K = 256; off = OFF_Q0;  break;
        case 4:  s = k0; K = 256; off = OFF_K0;  break;
        case 5:  s = v0; K = 256; off = OFF_V0;  break;
        case 6:  s = o0; K = 128; off = OFF_O0;  break;
        case 7:  s = q1; K = 256; off = OFF_Q1;  break;
        case 8:  s = k1; K = 256; off = OFF_K1;  break;
        case 9:  s = v1; K = 256; off = OFF_V1;  break;
        default: s = o1; K = 128; off = OFF_O1;  break;
    }
    int t = blockIdx.x * 256 + threadIdx.x;     // one thread = 4 half2 (n..n+3)
    if (t >= K * 16) return;
    int k2 = t >> 5;
    int n  = (t & 31) << 2;
    float4 lo = *reinterpret_cast<const float4*>(s + (2*k2    )*128 + n);
    float4 hi = *reinterpret_cast<const float4*>(s + (2*k2 + 1)*128 + n);
    uint4 u;
    u.x = f2h2(lo.x, hi.x);
    u.y = f2h2(lo.y, hi.y);
    u.z = f2h2(lo.z, hi.z);
    u.w = f2h2(lo.w, hi.w);
    *reinterpret_cast<uint4*>(&g_W16[off + k2*128 + n]) = u;
}

// ---------- 3-stage GEMM mainloop (dynamic smem) ----------
// layout: As[3][128][20] at dsm, Bs[3][16][136] at dsm+7680; total 14208 words
#define GSM_WORDS 14208
#define AS3(buf, r, c) dsm[(buf)*2560 + (r)*20 + (c)]
#define BS3(buf, r, c) dsm[7680 + (buf)*2176 + (r)*136 + (c)]

__device__ __forceinline__ void hgemm_mainloop(
    uint32_t* dsm,
    const __half* A1, const __half* A2, int K1, int K,
    const __half2* W2, float acc[2][8][4], int row0)
{
    const int tid  = threadIdx.x;
    const int lane = tid & 31;
    const int w    = tid >> 5;
    const int wm   = w & 3;
    const int wn   = w >> 2;
    const int lr   = lane >> 2;
    const int lc   = lane & 3;
    const int sa_r   = tid >> 1;
    const int sa_k16 = (tid & 1) << 4;

#define CP_A(k0, bufi)                                                         \
    {                                                                          \
        int kg = (k0) + sa_k16;                                                \
        const __half* src = (kg < K1) ? A1 : A2;                               \
        int kk     = (kg < K1) ? kg : (kg - K1);                               \
        int stride = (kg < K1) ? K1 : (K - K1);                                \
        const __half* p = src + (size_t)(row0 + sa_r) * stride + kk;           \
        uint32_t d = smem_u32(&AS3(bufi, sa_r, sa_k16 >> 1));                  \
        cp16(d, p);                                                            \
        cp16(d + 16, p + 8);                                                   \
    }

#define CP_B(k0, bufi)                                                         \
    {                                                                          \
        _Pragma("unroll")                                                      \
        for (int i = 0; i < 2; ++i) {                                          \
            int idx = tid + i * 256;                                           \
            int k2r = idx >> 5, nq = (idx & 31) << 2;                          \
            cp16(smem_u32(&BS3(bufi, k2r, nq)),                                \
                 W2 + (size_t)(((k0) >> 1) + k2r) * 128 + nq);                 \
        }                                                                      \
    }

#pragma unroll
    for (int mt = 0; mt < 2; ++mt)
#pragma unroll
        for (int nt = 0; nt < 8; ++nt)
#pragma unroll
            for (int i = 0; i < 4; ++i) acc[mt][nt][i] = 0.f;

    CP_A(0, 0);
    CP_B(0, 0);
    cp_commit();
    if (K > 32) {
        CP_A(32, 1);
        CP_B(32, 1);
        cp_commit();
    }

    int s = 0;
    for (int k0 = 0; k0 < K; k0 += 32, ++s) {
        if (k0 + 32 < K) cp_wait1(); else cp_wait0();
        __syncthreads();

        if (k0 + 64 < K) {
            const int nb = (s + 2) % 3;      // FIXED: proper mod-3 ring index
            CP_A(k0 + 64, nb);
            CP_B(k0 + 64, nb);
            cp_commit();
        }

        const int b3 = s % 3;
#pragma unroll
        for (int sx = 0; sx < 2; ++sx) {
            uint32_t a[2][4], b[8][2];
#pragma unroll
            for (int mt = 0; mt < 2; ++mt) {
                int rm = wm*32 + mt*16 + lr;
                a[mt][0] = AS3(b3, rm    , sx*8 + lc    );
                a[mt][1] = AS3(b3, rm + 8, sx*8 + lc    );
                a[mt][2] = AS3(b3, rm    , sx*8 + lc + 4);
                a[mt][3] = AS3(b3, rm + 8, sx*8 + lc + 4);
            }
#pragma unroll
            for (int nt = 0; nt < 8; ++nt) {
                int nb2 = wn*64 + nt*8 + lr;
                b[nt][0] = BS3(b3, sx*8 + lc    , nb2);
                b[nt][1] = BS3(b3, sx*8 + lc + 4, nb2);
            }
#pragma unroll
            for (int mt = 0; mt < 2; ++mt)
#pragma unroll
                for (int nt = 0; nt < 8; ++nt)
                    mma_f16(acc[mt][nt], a[mt], b[nt], acc[mt][nt]);
        }
    }
#undef CP_A
#undef CP_B
}

__device__ __forceinline__ void hgemm_body(
    uint32_t* dsm,
    const __half* A1, const __half* A2, int K1, int K,
    const __half2* W2, const float* bias,
    const __half* base, __half* C, int relu, int row0)
{
    const int tid  = threadIdx.x;
    const int lane = tid & 31;
    const int w    = tid >> 5;
    const int wm   = w & 3;
    const int wn   = w >> 2;
    const int lr   = lane >> 2;
    const int lc   = lane & 3;

    float acc[2][8][4];
    hgemm_mainloop(dsm, A1, A2, K1, K, W2, acc, row0);

#pragma unroll
    for (int mt = 0; mt < 2; ++mt) {
#pragma unroll
        for (int nt = 0; nt < 8; ++nt) {
            int col = wn*64 + nt*8 + 2*lc;
            float b0 = bias[col], b1 = bias[col+1];
#pragma unroll
            for (int half = 0; half < 2; ++half) {
                int row = row0 + wm*32 + mt*16 + lr + half*8;
                float v0 = acc[mt][nt][half*2+0] + b0;
                float v1 = acc[mt][nt][half*2+1] + b1;
                if (relu) { v0 = fmaxf(v0, 0.f); v1 = fmaxf(v1, 0.f); }
                if (base) {
                    __half2 bh = *reinterpret_cast<const __half2*>(
                        base + (size_t)row * 128 + col);
                    float2 bf = __half22float2(bh);
                    v0 += bf.x; v1 += bf.y;
                }
                *reinterpret_cast<uint32_t*>(C + (size_t)row * 128 + col) =
                    f2h2(v0, v1);
            }
        }
    }
}

__global__ __launch_bounds__(256) void hgemm_kernel(
    const __half* __restrict__ A1, const __half* __restrict__ A2, int K1, int K,
    const __half2* __restrict__ W2, const float* __restrict__ bias,
    const __half* __restrict__ base, __half* __restrict__ C, int relu)
{
    extern __shared__ uint32_t dsm[];
    hgemm_body(dsm, A1, A2, K1, K, W2, bias, base, C, relu, blockIdx.x << 7);
}

// batched q/k/v: blockIdx.y selects the matrix
__global__ __launch_bounds__(256) void qkv3_kernel(
    const __half* __restrict__ A1, const __half* __restrict__ A2,
    const __half2* __restrict__ Wq, const __half2* __restrict__ Wk,
    const __half2* __restrict__ Wv,
    const float* __restrict__ bq, const float* __restrict__ bk,
    const float* __restrict__ bv,
    __half* __restrict__ Oq, __half* __restrict__ Ok, __half* __restrict__ Ov)
{
    extern __shared__ uint32_t dsm[];
    const int m = blockIdx.y;
    const __half2* W2 = (m == 0) ? Wq : (m == 1) ? Wk : Wv;
    const float* bias = (m == 0) ? bq : (m == 1) ? bk : bv;
    __half* C         = (m == 0) ? Oq : (m == 1) ? Ok : Ov;
    hgemm_body(dsm, A1, A2, 128, 256, W2, bias, nullptr, C, 0, blockIdx.x << 7);
}

// ==== final O-projection fused with residual add + classifier ====
__global__ __launch_bounds__(256) void ofinal_kernel(
    const __half* __restrict__ A1, const __half2* __restrict__ W2,
    const float* __restrict__ bias, const __half* __restrict__ base,
    const float* __restrict__ Wfin, const float* __restrict__ bfin,
    float* __restrict__ out)
{
    extern __shared__ uint32_t dsm[];
    __shared__ float Wf[256];
    __shared__ float bf2[2];

    const int tid  = threadIdx.x;
    const int lane = tid & 31;
    const int w    = tid >> 5;
    const int wm   = w & 3;
    const int wn   = w >> 2;
    const int lr   = lane >> 2;
    const int lc   = lane & 3;
    const int row0 = blockIdx.x << 7;

    if (tid < 256) Wf[tid] = Wfin[tid];
    if (tid < 2)   bf2[tid] = bfin[tid];

    float acc[2][8][4];
    hgemm_mainloop(dsm, A1, A1, 128, 128, W2, acc, row0);

    __syncthreads();   // all staging reads complete before overlay

    // overlay hp tile [128 rows][64 half2 + pad] (needs 8448 <= 14208 words)
    uint32_t* ZS = dsm;
#define ZSX(r, c2) ZS[(r)*66 + (c2)]

#pragma unroll
    for (int mt = 0; mt < 2; ++mt) {
#pragma unroll
        for (int nt = 0; nt < 8; ++nt) {
            int col = wn*64 + nt*8 + 2*lc;
            float b0 = bias[col], b1 = bias[col+1];
#pragma unroll
            for (int half = 0; half < 2; ++half) {
                int row = wm*32 + mt*16 + lr + half*8;
                float v0 = fmaxf(acc[mt][nt][half*2+0] + b0, 0.f);
                float v1 = fmaxf(acc[mt][nt][half*2+1] + b1, 0.f);
                __half2 bh = *reinterpret_cast<const __half2*>(
                    base + (size_t)(row0 + row) * 128 + col);
                float2 bv = __half22float2(bh);
                v0 += bv.x; v1 += bv.y;
                ZSX(row, col >> 1) = f2h2(v0, v1);
            }
        }
    }
    __syncthreads();

    // classifier: thread t -> (row = t>>1, cls = t&1); identical order to final_kernel
    {
        int row = tid >> 1;
        int cls = tid & 1;
        float a = bf2[cls];
#pragma unroll
        for (int k2 = 0; k2 < 64; ++k2) {
            __half2 hv = *reinterpret_cast<__half2*>(&ZSX(row, k2));
            float2 f = __half22float2(hv);
            a += f.x * Wf[4*k2 + cls] + f.y * Wf[4*k2 + 2 + cls];
        }
        out[(size_t)(row0 + row) * 2 + cls] = a;
    }
#undef ZSX
}

// ====== fused diffusion + linear: Hout = relu((P16 @ Hin) @ Wd + bias) ======
template<int BN>
__global__ __launch_bounds__(256) void diff_fused_kernel(
    const __half* __restrict__ P, const __half* __restrict__ Hin,
    const __half2* __restrict__ Wd2, const float* __restrict__ bias,
    __half* __restrict__ Hout)
{
    constexpr int WN = BN / 2;
    constexpr int NT = WN / 8;
    constexpr int ZW = BN / 2 + 4;

    extern __shared__ uint32_t dsm[];
    uint32_t* AS = dsm;                    // [2][128][20]
    uint32_t* BS = dsm + 5120;             // [2][16][136]
    uint32_t* ZS = dsm + 5120 + 4352;      // [128][ZW]
#define ASX(bufi, r, c) AS[(bufi)*2560 + (r)*20 + (c)]
#define BSX(bufi, r, c) BS[(bufi)*2176 + (r)*136 + (c)]
#define ZSX(r, c)       ZS[(r)*ZW + (c)]

    const int tid  = threadIdx.x;
    const int lane = tid & 31;
    const int w    = tid >> 5;
    const int wm   = w & 3;
    const int wn   = w >> 2;
    const int lr   = lane >> 2;
    const int lc   = lane & 3;
    const int b    = blockIdx.z;
    const int i0   = blockIdx.x << 7;
    const size_t pb = (size_t)b * NN2;
    const size_t hb = (size_t)b * NNODE * BN;

    const int sa_r   = tid >> 1;
    const int sa_k16 = (tid & 1) << 4;

    uint4 bu0, bu1;

#define CP_P(j0, bufi)                                                         \
    {                                                                          \
        const __half* p = P + pb + (size_t)(i0 + sa_r) * NNODE + (j0) + sa_k16;\
        uint32_t d = smem_u32(&ASX(bufi, sa_r, sa_k16 >> 1));                  \
        cp16(d, p);                                                            \
        cp16(d + 16, p + 8);                                                   \
    }

#define DIFF_LDG_B(j0)                                                         \
    {                                                                          \
        if (BN == 128) {                                                       \
            int k2r = tid >> 4, nh = (tid & 15) * 8;                           \
            const __half* q = Hin + hb + (size_t)((j0) + 2*k2r) * BN + nh;     \
            bu0 = *reinterpret_cast<const uint4*>(q);                          \
            bu1 = *reinterpret_cast<const uint4*>(q + BN);                     \
        } else {                                                               \
            int k2r = tid >> 4, nh = (tid & 15) * 4;                           \
            const __half* q = Hin + hb + (size_t)((j0) + 2*k2r) * BN + nh;     \
            uint2 t0 = *reinterpret_cast<const uint2*>(q);                     \
            uint2 t1 = *reinterpret_cast<const uint2*>(q + BN);                \
            bu0.x = t0.x; bu0.y = t0.y; bu1.x = t1.x; bu1.y = t1.y;            \
        }                                                                      \
    }

#define DIFF_STS_B(bufi)                                                       \
    {                                                                          \
        if (BN == 128) {                                                       \
            int k2r = tid >> 4, nh = (tid & 15) * 8;                           \
            uint4 v0, v1;                                                      \
            v0.x = __byte_perm(bu0.x, bu1.x, 0x5410);                          \
            v0.y = __byte_perm(bu0.x, bu1.x, 0x7632);                          \
            v0.z = __byte_perm(bu0.y, bu1.y, 0x5410);                          \
            v0.w = __byte_perm(bu0.y, bu1.y, 0x7632);                          \
            v1.x = __byte_perm(bu0.z, bu1.z, 0x5410);                          \
            v1.y = __byte_perm(bu0.z, bu1.z, 0x7632);                          \
            v1.z = __byte_perm(bu0.w, bu1.w, 0x5410);                          \
            v1.w = __byte_perm(bu0.w, bu1.w, 0x7632);                          \
            *reinterpret_cast<uint4*>(&BSX(bufi, k2r, nh    )) = v0;           \
            *reinterpret_cast<uint4*>(&BSX(bufi, k2r, nh + 4)) = v1;           \
        } else {                                                               \
            int k2r = tid >> 4, nh = (tid & 15) * 4;                           \
            uint4 v0;                                                          \
            v0.x = __byte_perm(bu0.x, bu1.x, 0x5410);                          \
            v0.y = __byte_perm(bu0.x, bu1.x, 0x7632);                          \
            v0.z = __byte_perm(bu0.y, bu1.y, 0x5410);                          \
            v0.w = __byte_perm(bu0.y, bu1.y, 0x7632);                          \
            *reinterpret_cast<uint4*>(&BSX(bufi, k2r, nh)) = v0;               \
        }                                                                      \
    }

    // ---------------- phase 1: z = P @ Hin ----------------
    float acc[2][NT][4];
#pragma unroll
    for (int mt = 0; mt < 2; ++mt)
#pragma unroll
        for (int nt = 0; nt < NT; ++nt)
#pragma unroll
            for (int i = 0; i < 4; ++i) acc[mt][nt][i] = 0.f;

    DIFF_LDG_B(0);
    CP_P(0, 0);
    cp_commit();
    DIFF_STS_B(0);

    int buf = 0;
    for (int j0 = 0; j0 < NNODE; j0 += 32) {
        cp_wait0();
        __syncthreads();
        const bool has_next = (j0 + 32 < NNODE);
        if (has_next) {
            CP_P(j0 + 32, buf ^ 1);
            cp_commit();
            DIFF_LDG_B(j0 + 32);
        }
#pragma unroll
        for (int s = 0; s < 2; ++s) {
            uint32_t a[2][4], bf[NT][2];
#pragma unroll
            for (int mt = 0; mt < 2; ++mt) {
                int rm = wm*32 + mt*16 + lr;
                a[mt][0] = ASX(buf, rm    , s*8 + lc    );
                a[mt][1] = ASX(buf, rm + 8, s*8 + lc    );
                a[mt][2] = ASX(buf, rm    , s*8 + lc + 4);
                a[mt][3] = ASX(buf, rm + 8, s*8 + lc + 4);
            }
#pragma unroll
            for (int nt = 0; nt < NT; ++nt) {
                int nb = wn*WN + nt*8 + lr;
                bf[nt][0] = BSX(buf, s*8 + lc    , nb);
                bf[nt][1] = BSX(buf, s*8 + lc + 4, nb);
            }
#pragma unroll
            for (int mt = 0; mt < 2; ++mt)
#pragma unroll
                for (int nt = 0; nt < NT; ++nt)
                    mma_f16(acc[mt][nt], a[mt], bf[nt], acc[mt][nt]);
        }
        if (has_next) DIFF_STS_B(buf ^ 1);
        buf ^= 1;
    }

#pragma unroll
    for (int mt = 0; mt < 2; ++mt) {
#pragma unroll
        for (int nt = 0; nt < NT; ++nt) {
            int col = wn*WN + nt*8 + 2*lc;
#pragma unroll
            for (int half = 0; half < 2; ++half) {
                int row = wm*32 + mt*16 + lr + half*8;
                ZSX(row, col >> 1) =
                    f2h2(acc[mt][nt][half*2+0], acc[mt][nt][half*2+1]);
            }
        }
    }
    __syncthreads();

    // ---------------- phase 2: Hout = relu(z @ Wd + bias) ----------------
#define CP_W(k0, bufi)                                                         \
    {                                                                          \
        _Pragma("unroll")                                                      \
        for (int i = 0; i < 2; ++i) {                                          \
            int idx = tid + i * 256;                                           \
            int k2r = idx >> 5, nq = (idx & 31) << 2;                          \
            cp16(smem_u32(&BSX(bufi, k2r, nq)),                                \
                 Wd2 + (size_t)(((k0) >> 1) + k2r) * 128 + nq);                \
        }                                                                      \
    }

    float acc2[2][8][4];
#pragma unroll
    for (int mt = 0; mt < 2; ++mt)
#pragma unroll
        for (int nt = 0; nt < 8; ++nt)
#pragma unroll
            for (int i = 0; i < 4; ++i) acc2[mt][nt][i] = 0.f;

    CP_W(0, 0);
    cp_commit();

    buf = 0;
    for (int k0 = 0; k0 < BN; k0 += 32) {
        cp_wait0();
        __syncthreads();
        const bool has_next = (k0 + 32 < BN);
        if (has_next) {
            CP_W(k0 + 32, buf ^ 1);
            cp_commit();
        }
        const int k2b = k0 >> 1;
#pragma unroll
        for (int s = 0; s < 2; ++s) {
            uint32_t a[2][4], bfr[8][2];
#pragma unroll
            for (int mt = 0; mt < 2; ++mt) {
                int rm = wm*32 + mt*16 + lr;
                a[mt][0] = ZSX(rm    , k2b + s*8 + lc    );
                a[mt][1] = ZSX(rm + 8, k2b + s*8 + lc    );
                a[mt][2] = ZSX(rm    , k2b + s*8 + lc + 4);
                a[mt][3] = ZSX(rm + 8, k2b + s*8 + lc + 4);
            }
#pragma unroll
            for (int nt = 0; nt < 8; ++nt) {
                int nb = wn*64 + nt*8 + lr;
                bfr[nt][0] = BSX(buf, s*8 + lc    , nb);
                bfr[nt][1] = BSX(buf, s*8 + lc + 4, nb);
            }
#pragma unroll
            for (int mt = 0; mt < 2; ++mt)
#pragma unroll
                for (int nt = 0; nt < 8; ++nt)
                    mma_f16(acc2[mt][nt], a[mt], bfr[nt], acc2[mt][nt]);
        }
        buf ^= 1;
    }

#pragma unroll
    for (int mt = 0; mt < 2; ++mt) {
#pragma unroll
        for (int nt = 0; nt < 8; ++nt) {
            int col = wn*64 + nt*8 + 2*lc;
            float b0 = bias[col], b1 = bias[col+1];
#pragma unroll
            for (int half = 0; half < 2; ++half) {
                int row = i0 + wm*32 + mt*16 + lr + half*8;
                float v0 = fmaxf(acc2[mt][nt][half*2+0] + b0, 0.f);
                float v1 = fmaxf(acc2[mt][nt][half*2+1] + b1, 0.f);
                *reinterpret_cast<uint32_t*>(
                    Hout + ((size_t)b * NNODE + row) * 128 + col) = f2h2(v0, v1);
            }
        }
    }
#undef CP_P
#undef DIFF_LDG_B
#undef DIFF_STS_B
#undef CP_W
#undef ASX
#undef BSX
#undef ZSX
}

// ========== fp16 flash attention: 256 q / 512 thr; P register-resident ==========
__global__ __launch_bounds__(512) void attn_mma_kernel(
    const __half* __restrict__ Qg, const __half* __restrict__ Kg,
    const __half* __restrict__ Vg, __half* __restrict__ Og)
{
    extern __shared__ uint32_t asmem[];
    uint32_t (*Ps2)[36] = reinterpret_cast<uint32_t(*)[36]>(asmem);            // 256 rows (Q staging only)
    uint32_t (*Ks2)[36] = reinterpret_cast<uint32_t(*)[36]>(asmem + 256*36);   // 2*64 rows
    uint32_t (*Vs2)[72] = reinterpret_cast<uint32_t(*)[72]>(asmem + 384*36);   // 2*32 rows

    const int tid  = threadIdx.x;
    const int lane = tid & 31;
    const int w    = tid >> 5;
    const int lr   = lane >> 2;
    const int lc   = lane & 3;
    const int b    = blockIdx.z, h = blockIdx.y;
    const int q0   = blockIdx.x << 8;
    const size_t rb = (size_t)b * NNODE;
    const int hoff = h * 64;
    const float SC = 0.125f * 1.4426950408889634f;
    const __half2 h2sc = __float2half2_rn(SC);

    {
        int r   = w*16 + (lane >> 1);
        int seg = (lane & 1) * 32;
        const __half* p = Qg + (rb + q0 + r) * 128 + hoff + seg;
#pragma unroll
        for (int jj = 0; jj < 4; ++jj) {
            uint4 u = *reinterpret_cast<const uint4*>(p + 8*jj);
            *reinterpret_cast<uint4*>(&Ps2[r][(seg>>1) + 4*jj]) = u;
        }
    }
    __syncwarp();

    uint32_t qa[4][4];
#pragma unroll
    for (int ks = 0; ks < 4; ++ks) {
        qa[ks][0] = Ps2[w*16 + lr    ][ks*8 + lc    ];
        qa[ks][1] = Ps2[w*16 + lr + 8][ks*8 + lc    ];
        qa[ks][2] = Ps2[w*16 + lr    ][ks*8 + lc + 4];
        qa[ks][3] = Ps2[w*16 + lr + 8][ks*8 + lc + 4];
#pragma unroll
        for (int i = 0; i < 4; ++i) {
            __half2 hv = *reinterpret_cast<__half2*>(&qa[ks][i]);
            hv = __hmul2(hv, h2sc);
            qa[ks][i] = h2bits(hv);
        }
    }

    float m0 = -1e30f, m1 = -1e30f, l0 = 0.f, l1 = 0.f;
    float oacc[8][4];
#pragma unroll
    for (int nt = 0; nt < 8; ++nt)
#pragma unroll
        for (int i = 0; i < 4; ++i) oacc[nt][i] = 0.f;

    uint2 uv0, uv1;
    const int kr   = tid >> 3;
    const int kseg = (tid & 7) << 3;
    const int vk2r = tid >> 4;
    const int vdq  = (tid & 15) * 4;

#define CP_K(j0, bufi)                                                         \
    {                                                                          \
        const __half* p = Kg + (rb + (j0) + kr) * 128 + hoff + kseg;           \
        cp16(smem_u32(&Ks2[(bufi)*64 + kr][kseg >> 1]), p);                    \
    }

#define LDG_V(j0)                                                              \
    {                                                                          \
        const __half* q = Vg + (rb + (j0) + 2*vk2r) * 128 + hoff + vdq;        \
        uv0 = *reinterpret_cast<const uint2*>(q);                              \
        uv1 = *reinterpret_cast<const uint2*>(q + 128);                        \
    }

#define STS_V(bufi)                                                            \
    {                                                                          \
        uint4 v0;                                                              \
        v0.x = __byte_perm(uv0.x, uv1.x, 0x5410);                              \
        v0.y = __byte_perm(uv0.x, uv1.x, 0x7632);                              \
        v0.z = __byte_perm(uv0.y, uv1.y, 0x5410);                              \
        v0.w = __byte_perm(uv0.y, uv1.y, 0x7632);                              \
        *reinterpret_cast<uint4*>(&Vs2[(bufi)*32 + vk2r][vdq]) = v0;           \
    }

    CP_K(0, 0);
    cp_commit();
    LDG_V(0);
    STS_V(0);

    for (int c = 0; c < NNODE/64; ++c) {
        const int buf = c & 1;
        cp_wait0();
        __syncthreads();

        const bool has_next = (c + 1 < NNODE/64);
        if (has_next) {
            CP_K((c + 1) * 64, buf ^ 1);
            cp_commit();
            LDG_V((c + 1) * 64);
        }

        float sacc[8][4];
#pragma unroll
        for (int nt = 0; nt < 8; ++nt)
#pragma unroll
            for (int i = 0; i < 4; ++i) sacc[nt][i] = 0.f;
#pragma unroll
        for (int ks = 0; ks < 4; ++ks) {
#pragma unroll
            for (int nt = 0; nt < 8; ++nt) {
                uint32_t bf[2];
                bf[0] = Ks2[buf*64 + nt*8 + lr][ks*8 + lc    ];
                bf[1] = Ks2[buf*64 + nt*8 + lr][ks*8 + lc + 4];
                mma_f16(sacc[nt], qa[ks], bf, sacc[nt]);
            }
        }

        float rmax0 = -1e30f, rmax1 = -1e30f;
#pragma unroll
        for (int nt = 0; nt < 8; ++nt) {
            rmax0 = fmaxf(rmax0, fmaxf(sacc[nt][0], sacc[nt][1]));
            rmax1 = fmaxf(rmax1, fmaxf(sacc[nt][2], sacc[nt][3]));
        }
        rmax0 = fmaxf(rmax0, __shfl_xor_sync(0xffffffffu, rmax0, 1));
        rmax0 = fmaxf(rmax0, __shfl_xor_sync(0xffffffffu, rmax0, 2));
        rmax1 = fmaxf(rmax1, __shfl_xor_sync(0xffffffffu, rmax1, 1));
        rmax1 = fmaxf(rmax1, __shfl_xor_sync(0xffffffffu, rmax1, 2));

        float mn0 = fmaxf(m0, rmax0), mn1 = fmaxf(m1, rmax1);
        float cr0 = ex2f(m0 - mn0), cr1 = ex2f(m1 - mn1);
        m0 = mn0; m1 = mn1;

        uint32_t ph0[8], ph1[8];
        float rs0 = 0.f, rs1 = 0.f;
#pragma unroll
        for (int nt = 0; nt < 8; ++nt) {
            float p00 = ex2f(sacc[nt][0] - mn0);
            float p01 = ex2f(sacc[nt][1] - mn0);
            float p10 = ex2f(sacc[nt][2] - mn1);
            float p11 = ex2f(sacc[nt][3] - mn1);
            __half2 h0 = __floats2half2_rn(p00, p01);
            __half2 h1 = __floats2half2_rn(p10, p11);
            float2 f0 = __half22float2(h0);
            float2 f1 = __half22float2(h1);
            rs0 += f0.x + f0.y;
            rs1 += f1.x + f1.y;
            ph0[nt] = h2bits(h0);
            ph1[nt] = h2bits(h1);
        }
        rs0 += __shfl_xor_sync(0xffffffffu, rs0, 1);
        rs0 += __shfl_xor_sync(0xffffffffu, rs0, 2);
        rs1 += __shfl_xor_sync(0xffffffffu, rs1, 1);
        rs1 += __shfl_xor_sync(0xffffffffu, rs1, 2);
        l0 = l0 * cr0 + rs0;
        l1 = l1 * cr1 + rs1;

#pragma unroll
        for (int nt = 0; nt < 8; ++nt) {
            oacc[nt][0] *= cr0; oacc[nt][1] *= cr0;
            oacc[nt][2] *= cr1; oacc[nt][3] *= cr1;
        }

        if (has_next) STS_V(buf ^ 1);

#pragma unroll
        for (int ks = 0; ks < 4; ++ks) {
            uint32_t pa[4];
            pa[0] = ph0[2*ks    ];
            pa[1] = ph1[2*ks    ];
            pa[2] = ph0[2*ks + 1];
            pa[3] = ph1[2*ks + 1];
#pragma unroll
            for (int nt = 0; nt < 8; ++nt) {
                uint32_t bf[2];
                bf[0] = Vs2[buf*32 + ks*8 + lc    ][nt*8 + lr];
                bf[1] = Vs2[buf*32 + ks*8 + lc + 4][nt*8 + lr];
                mma_f16(oacc[nt], pa, bf, oacc[nt]);
            }
        }
    }

    float inv0 = 1.f / l0, inv1 = 1.f / l1;
#pragma unroll
    for (int nt = 0; nt < 8; ++nt) {
        int col = hoff + nt*8 + 2*lc;
        *reinterpret_cast<uint32_t*>(Og + (rb + q0 + w*16 + lr    ) * 128 + col) =
            f2h2(oacc[nt][0] * inv0, oacc[nt][1] * inv0);
        *reinterpret_cast<uint32_t*>(Og + (rb + q0 + w*16 + lr + 8) * 128 + col) =
            f2h2(oacc[nt][2] * inv1, oacc[nt][3] * inv1);
    }
#undef CP_K
#undef LDG_V
#undef STS_V
}

// ---------------- launch ----------------
extern "C" void kernel_launch(void* const* d_in, const int* in_sizes, int n_in,
                              void* d_out, int out_size) {
    const float* X     = (const float*)d_in[0];
    const float* A     = (const float*)d_in[1];
    const float* T     = (const float*)d_in[2];
    const float* theta = (const float*)d_in[3];
    const float* W_raw = (const float*)d_in[4];
    const float* b_raw = (const float*)d_in[5];
    const float* Wd0   = (const float*)d_in[6];
    const float* bd0   = (const float*)d_in[7];
    const float* Wd1   = (const float*)d_in[8];
    const float* bd1   = (const float*)d_in[9];
    const float* W_fin = (const float*)d_in[10];
    const float* b_fin = (const float*)d_in[11];
    const float* Wq0 = (const float*)d_in[12]; const float* bq0 = (const float*)d_in[13];
    const float* Wk0 = (const float*)d_in[14]; const float* bk0 = (const float*)d_in[15];
    const float* Wv0 = (const float*)d_in[16]; const float* bv0 = (const float*)d_in[17];
    const float* Wo0 = (const float*)d_in[18]; const float* bo0 = (const float*)d_in[19];
    const float* Wq1 = (const float*)d_in[20]; const float* bq1 = (const float*)d_in[21];
    const float* Wk1 = (const float*)d_in[22]; const float* bk1 = (const float*)d_in[23];
    const float* Wv1 = (const float*)d_in[24]; const float* bv1 = (const float*)d_in[25];
    const float* Wo1 = (const float*)d_in[26]; const float* bo1 = (const float*)d_in[27];

    __half *P0, *P1, *X16, *hp, *h, *h2, *qb, *kb, *vb, *ctx;
    __half2* W16;
    cudaGetSymbolAddress((void**)&P0,  g_P0);
    cudaGetSymbolAddress((void**)&P1,  g_P1);
    cudaGetSymbolAddress((void**)&X16, g_X16);
    cudaGetSymbolAddress((void**)&hp,  g_hp);
    cudaGetSymbolAddress((void**)&h,   g_h);
    cudaGetSymbolAddress((void**)&h2,  g_h2);
    cudaGetSymbolAddress((void**)&qb,  g_qb);
    cudaGetSymbolAddress((void**)&kb,  g_kb);
    cudaGetSymbolAddress((void**)&vb,  g_vb);
    cudaGetSymbolAddress((void**)&ctx, g_ctx);
    cudaGetSymbolAddress((void**)&W16, g_W16);

    const int gemm_smem  = GSM_WORDS * (int)sizeof(uint32_t);                 // 56832
    const int attn_smem  = (256*36 + 128*36 + 64*72) * (int)sizeof(uint32_t); // 73728
    const int diff64_sm  = (5120 + 4352 + 128*36) * (int)sizeof(uint32_t);    // 56320
    const int diff128_sm = (5120 + 4352 + 128*68) * (int)sizeof(uint32_t);    // 72704
    cudaFuncSetAttribute(hgemm_kernel,
        cudaFuncAttributeMaxDynamicSharedMemorySize, gemm_smem);
    cudaFuncSetAttribute(qkv3_kernel,
        cudaFuncAttributeMaxDynamicSharedMemorySize, gemm_smem);
    cudaFuncSetAttribute(ofinal_kernel,
        cudaFuncAttributeMaxDynamicSharedMemorySize, gemm_smem);
    cudaFuncSetAttribute(attn_mma_kernel,
        cudaFuncAttributeMaxDynamicSharedMemorySize, attn_smem);
    cudaFuncSetAttribute(diff_fused_kernel<64>,
        cudaFuncAttributeMaxDynamicSharedMemorySize, diff64_sm);
    cudaFuncSetAttribute(diff_fused_kernel<128>,
        cudaFuncAttributeMaxDynamicSharedMemorySize, diff128_sm);

    const int ggrid = M_ROWS / 128;
    dim3 dgrid(NNODE / 128, 1, NB);
    dim3 qkv_grid(ggrid, 3);
    dim3 attn_grid(NNODE / 256, 2, NB);

    qmix_kernel<<<2 * 1024 * 1024 / 256, 256>>>(T, theta);
    pmul_kernel<<<NB * 1024 * 1024 / 1024, 256>>>(A);
    tohalf_kernel<<<M_ROWS * 64 / 1024, 256>>>(X, X16);
    wconv_kernel<<<dim3(16, 11), 256>>>(W_raw, Wd0, Wd1,
                                        Wq0, Wk0, Wv0, Wo0,
                                        Wq1, Wk1, Wv1, Wo1);

    // raw projection: hp = X @ W_raw + b_raw
    hgemm_kernel<<<ggrid, 256, gemm_smem>>>(X16, X16, 64, 64,
                                            W16 + OFF_RAW, b_raw, nullptr, hp, 0);

    // layer 0: fused diffusion+linear, then attention block
    diff_fused_kernel<64><<<dgrid, 256, diff64_sm>>>(P0, X16, W16 + OFF_D0, bd0, h);
    qkv3_kernel<<<qkv_grid, 256, gemm_smem>>>(h, hp,
                                   W16 + OFF_Q0, W16 + OFF_K0, W16 + OFF_V0,
                                   bq0, bk0, bv0, qb, kb, vb);
    attn_mma_kernel<<<attn_grid, 512, attn_smem>>>(qb, kb, vb, ctx);
    hgemm_kernel<<<ggrid, 256, gemm_smem>>>(ctx, ctx, 128, 128,
                                            W16 + OFF_O0, bo0, nullptr, hp, 1);

    // layer 1 (no aliasing: diff writes h2)
    diff_fused_kernel<128><<<dgrid, 256, diff128_sm>>>(P1, h, W16 + OFF_D1, bd1, h2);
    qkv3_kernel<<<qkv_grid, 256, gemm_smem>>>(h2, hp,
                                   W16 + OFF_Q1, W16 + OFF_K1, W16 + OFF_V1,
                                   bq1, bk1, bv1, qb, kb, vb);
    attn_mma_kernel<<<attn_grid, 512, attn_smem>>>(qb, kb, vb, ctx);

    // final O-projection fused with residual add + classifier
    ofinal_kernel<<<ggrid, 256, gemm_smem>>>(ctx, W16 + OFF_O1, bo1, hp,
                                             W_fin, b_fin, (float*)d_out);
}